// round 13
// baseline (speedup 1.0000x reference)
#include <cuda_runtime.h>
#include <cuda_fp16.h>
#include <cstdint>

#define BB 4
#define SS 1024
#define DD 1024
#define HH 16
#define DK 64
#define NEL (BB * HH * SS * DK)   // 4M

// Scratch (__device__ globals)
__device__ __half g_qin[NEL], g_kin[NEL], g_vin[NEL];   // fp16 input copies [B,S,D]
__device__ __half g_w[4 * DD * DD];                     // fp16 weights [k][n] (4 mats)
__device__ __half g_q[NEL];          // [bh][s][d]
__device__ __half g_k[NEL];          // [bh][r][u][d]
__device__ __half g_v[NEL];          // [bh][r][u][d]
__device__ __half g_attn[BB * SS * DD];                 // fp16 attention out [B,S,D]

// ---------------------------------------------------------------------------
__device__ __forceinline__ unsigned saddr(const void* p) {
    return (unsigned)__cvta_generic_to_shared(p);
}
__device__ __forceinline__ void ldm_x4(uint32_t* r, const void* p) {
    asm volatile("ldmatrix.sync.aligned.m8n8.x4.shared.b16 {%0,%1,%2,%3}, [%4];"
        : "=r"(r[0]), "=r"(r[1]), "=r"(r[2]), "=r"(r[3]) : "r"(saddr(p)));
}
__device__ __forceinline__ void ldm_x4_t(uint32_t* r, const void* p) {
    asm volatile("ldmatrix.sync.aligned.m8n8.x4.trans.shared.b16 {%0,%1,%2,%3}, [%4];"
        : "=r"(r[0]), "=r"(r[1]), "=r"(r[2]), "=r"(r[3]) : "r"(saddr(p)));
}
__device__ __forceinline__ void mma16816(float* c, const uint32_t* a, const uint32_t* b) {
    asm volatile("mma.sync.aligned.m16n8k16.row.col.f32.f16.f16.f32 "
        "{%0,%1,%2,%3},{%4,%5,%6,%7},{%8,%9},{%0,%1,%2,%3};"
        : "+f"(c[0]), "+f"(c[1]), "+f"(c[2]), "+f"(c[3])
        : "r"(a[0]), "r"(a[1]), "r"(a[2]), "r"(a[3]), "r"(b[0]), "r"(b[1]));
}
__device__ __forceinline__ void cp_async16(void* s, const void* g) {
    asm volatile("cp.async.cg.shared.global [%0], [%1], 16;"
        :: "r"(saddr(s)), "l"(g));
}
#define CP_COMMIT() asm volatile("cp.async.commit_group;" ::: "memory")
#define CP_WAIT(n)  asm volatile("cp.async.wait_group %0;" :: "n"(n) : "memory")

__device__ __forceinline__ uint32_t packh2(float a, float b) {
    __half2 p = __floats2half2_rn(a, b);
    return *(uint32_t*)&p;
}

// ---------------------------------------------------------------------------
// Fused prep: all fp32->fp16 in ONE launch, 4 float4 per thread (MLP=4).
// ---------------------------------------------------------------------------
__global__ void __launch_bounds__(256) convall_kernel(
    const float* __restrict__ Q, const float* __restrict__ K,
    const float* __restrict__ V,
    const float* __restrict__ W0, const float* __restrict__ W1,
    const float* __restrict__ W2, const float* __restrict__ W3,
    __half* __restrict__ dq, __half* __restrict__ dk, __half* __restrict__ dv,
    __half* __restrict__ dw)
{
    int b = blockIdx.x;
    const float* src;
    __half* dst;
    int lb;
    if (b < 1024)       { src = Q; dst = dq; lb = b; }
    else if (b < 2048)  { src = K; dst = dk; lb = b - 1024; }
    else if (b < 3072)  { src = V; dst = dv; lb = b - 2048; }
    else {
        int wb = b - 3072;
        int wz = wb >> 8;
        src = (wz == 0) ? W0 : (wz == 1) ? W1 : (wz == 2) ? W2 : W3;
        dst = dw + (size_t)wz * DD * DD;
        lb = wb & 255;
    }
    float4 v[4];
    size_t base = (size_t)lb * 1024 + threadIdx.x;
#pragma unroll
    for (int it = 0; it < 4; it++)
        v[it] = *(const float4*)(src + (base + it * 256) * 4);
#pragma unroll
    for (int it = 0; it < 4; it++) {
        uint2 u; u.x = packh2(v[it].x, v[it].y); u.y = packh2(v[it].z, v[it].w);
        *(uint2*)(dst + (base + it * 256) * 4) = u;
    }
}

// ---------------------------------------------------------------------------
// fp16 GEMM body: BK=64, 2-stage cp.async, 256 thr, 64x32 warp tiles,
// WPAD=136 (272B row stride -> conflict-free W ldmatrix), 3 CTAs/SM.
// ---------------------------------------------------------------------------
#define APAD 72              // 144B row stride (conflict-free)
#define WPAD 136             // 272B row stride (conflict-free, was 288B=2-way)
#define A_SZ (128 * APAD)
#define W_SZ (64 * WPAD)
#define STAGES 2
#define GEMM_SMEM (STAGES * (A_SZ + W_SZ) * 2)   // 71,680 bytes -> 3 CTAs/SM

__device__ __forceinline__ void store2(
    float* __restrict__ C, __half* __restrict__ O, int mode,
    int m, int n, float v0, float v1)
{
    if (mode == 0) {
        *(float2*)(C + (size_t)m * 1024 + n) = make_float2(v0, v1);
        return;
    }
    int b = m >> 10, s = m & 1023, h = n >> 6, d = n & 63;
    size_t idx;
    if (mode == 1) idx = (((size_t)(b * 16 + h)) * 1024 + s) * 64 + d;
    else           idx = ((((size_t)(b * 16 + h)) * 4 + (s & 3)) * 256 + (s >> 2)) * 64 + d;
    __half2 p = __floats2half2_rn(v0, v1);
    *(__half2*)(O + idx) = p;
}

__device__ __forceinline__ void gemm_body(
    const __half* __restrict__ A, const __half* __restrict__ Wm,
    const float* __restrict__ bias, float* __restrict__ C,
    __half* __restrict__ O, int mode, __half* smem)
{
    __half* sA = smem;                       // [STAGES][128][APAD]
    __half* sW = smem + STAGES * A_SZ;       // [STAGES][64][WPAD]

    const int tid = threadIdx.x;
    const int bm = blockIdx.y * 128, bn = blockIdx.x * 128;
    const int w = tid >> 5, lane = tid & 31;
    const int wm = (w & 1) * 64, wn = (w >> 1) * 32;
    const int lrow = lane & 15, lcol = (lane >> 4) << 3;

    float acc[4][4][4];
#pragma unroll
    for (int i = 0; i < 4; i++)
#pragma unroll
        for (int j = 0; j < 4; j++)
#pragma unroll
            for (int t = 0; t < 4; t++) acc[i][j][t] = 0.f;

    auto stage = [&](int buf, int k0) {
#pragma unroll
        for (int j = 0; j < 4; j++) {
            int c = tid + 256 * j;
            int arow = c >> 3, aco = (c & 7) * 8;
            cp_async16(&sA[buf * A_SZ + arow * APAD + aco],
                       A + (size_t)(bm + arow) * 1024 + k0 + aco);
            int wrow = c >> 4, wco = (c & 15) * 8;
            cp_async16(&sW[buf * W_SZ + wrow * WPAD + wco],
                       Wm + (size_t)(k0 + wrow) * 1024 + bn + wco);
        }
    };

    stage(0, 0);
    CP_COMMIT();

    for (int kt = 0; kt < 16; kt++) {
        CP_WAIT(0);
        __syncthreads();

        int nk = kt + 1;
        if (nk < 16) {
            stage(nk & 1, nk * 64);
            CP_COMMIT();
        }

        const __half* cA = sA + (kt & 1) * A_SZ;
        const __half* cW = sW + (kt & 1) * W_SZ;

#pragma unroll
        for (int kk = 0; kk < 64; kk += 16) {
            uint32_t a[4][4], b_[2][4];
#pragma unroll
            for (int mt = 0; mt < 4; mt++)
                ldm_x4(a[mt], &cA[(wm + mt * 16 + lrow) * APAD + kk + lcol]);
#pragma unroll
            for (int np = 0; np < 2; np++)
                ldm_x4_t(b_[np], &cW[(kk + lrow) * WPAD + wn + np * 16 + lcol]);
#pragma unroll
            for (int mt = 0; mt < 4; mt++)
#pragma unroll
                for (int nt = 0; nt < 4; nt++)
                    mma16816(acc[mt][nt], a[mt], &b_[nt >> 1][(nt & 1) * 2]);
        }
    }

    const int g = lane >> 2, t4 = lane & 3;
#pragma unroll
    for (int mt = 0; mt < 4; mt++)
#pragma unroll
        for (int nt = 0; nt < 4; nt++) {
            int m0 = bm + wm + mt * 16 + g;
            int n0 = bn + wn + nt * 8 + t4 * 2;
            float b0 = __ldg(bias + n0), b1 = __ldg(bias + n0 + 1);
            store2(C, O, mode, m0,     n0, acc[mt][nt][0] + b0, acc[mt][nt][1] + b1);
            store2(C, O, mode, m0 + 8, n0, acc[mt][nt][2] + b0, acc[mt][nt][3] + b1);
        }
}

__global__ void __launch_bounds__(256, 3) gemm_qkv_kernel(
    const __half* __restrict__ Aq, const __half* __restrict__ Ak,
    const __half* __restrict__ Av, const __half* __restrict__ Wall,
    const float* __restrict__ bq, const float* __restrict__ bk,
    const float* __restrict__ bv,
    __half* __restrict__ Oq, __half* __restrict__ Ok, __half* __restrict__ Ov)
{
    extern __shared__ __half smem[];
    int z = blockIdx.z;
    const __half* A = (z == 0) ? Aq : (z == 1) ? Ak : Av;
    const float* bias = (z == 0) ? bq : (z == 1) ? bk : bv;
    __half* O = (z == 0) ? Oq : (z == 1) ? Ok : Ov;
    gemm_body(A, Wall + (size_t)z * DD * DD, bias, nullptr, O,
              (z == 0) ? 1 : 2, smem);
}

__global__ void __launch_bounds__(256, 3) gemm_o_kernel(
    const __half* __restrict__ A, const __half* __restrict__ Wm,
    const float* __restrict__ bias, float* __restrict__ C)
{
    extern __shared__ __half smem[];
    gemm_body(A, Wm, bias, C, nullptr, 0, smem);
}

// ---------------------------------------------------------------------------
// Flash attention body (R10-proven inner code), pair-balanced blocks.
// ---------------------------------------------------------------------------
#define KVS 72

__device__ __forceinline__ void attn_body(
    const __half* __restrict__ qg, const __half* __restrict__ kg,
    const __half* __restrict__ vg, __half* __restrict__ out,
    __half* Qs, __half* Kb, __half* Vb, int bh, int r, int qt)
{
    const int tid = threadIdx.x, lane = tid & 31, w = tid >> 5;
    const int q0 = qt * 64;
    const int ntiles = qt + 1;

    const int wq = w * 16;
    const int g = lane >> 2, t4 = lane & 3;
    const int lrow = lane & 15, lcol = (lane >> 4) << 3;
    const int bnrow = ((lane >> 4) << 3) + (lane & 7);
    const int bkoff = ((lane >> 3) & 1) << 3;

    const __half* kbase = kg + (((size_t)bh * 4 + r) * 256) * 64;
    const __half* vbase = vg + (((size_t)bh * 4 + r) * 256) * 64;

#pragma unroll
    for (int j = 0; j < 4; j++) {
        int c = tid + 128 * j, row = c >> 3, co = (c & 7) * 8;
        int i = 4 * (q0 + row) + r;
        *(uint4*)&Qs[row * KVS + co] =
            *(const uint4*)(qg + ((size_t)bh * 1024 + i) * 64 + co);
    }
    __syncthreads();

    auto stage_kv = [&](int buf, int ut) {
#pragma unroll
        for (int j = 0; j < 4; j++) {
            int c = tid + 128 * j, row = c >> 3, co = (c & 7) * 8;
            cp_async16(&Kb[buf * 64 * KVS + row * KVS + co],
                       kbase + (size_t)(ut * 64 + row) * 64 + co);
            cp_async16(&Vb[buf * 64 * KVS + row * KVS + co],
                       vbase + (size_t)(ut * 64 + row) * 64 + co);
        }
    };
    stage_kv(0, 0);
    CP_COMMIT();

    uint32_t qf[4][4];
#pragma unroll
    for (int ks = 0; ks < 4; ks++)
        ldm_x4(qf[ks], &Qs[(wq + lrow) * KVS + ks * 16 + lcol]);

    const int i_g  = 4 * (q0 + wq + g) + r;
    const int i_g8 = i_g + 32;
    float m_g, m_g8, l_g, l_g8;
    float oacc[8][4];
#pragma unroll
    for (int nt = 0; nt < 8; nt++)
#pragma unroll
        for (int c = 0; c < 4; c++) oacc[nt][c] = 0.f;
    {
        float sg[3], sg8[3];
        const int nl_g = min(i_g, 3), nl_g8 = min(i_g8, 3);
#pragma unroll
        for (int l = 0; l < 3; l++) {
            float d0 = 0.f, d1 = 0.f;
            int jg = i_g - 1 - l, jg8 = i_g8 - 1 - l;
            if (l < nl_g) {
                const __half* kp = kg + ((((size_t)bh * 4 + (jg & 3)) * 256 + (jg >> 2)) * 64);
#pragma unroll
                for (int d = 0; d < 16; d += 2) {
                    __half2 a = *(const __half2*)&Qs[(wq + g) * KVS + t4 * 16 + d];
                    __half2 b = *(const __half2*)(kp + t4 * 16 + d);
                    d0 += __half2float(a.x) * __half2float(b.x)
                        + __half2float(a.y) * __half2float(b.y);
                }
            }
            if (l < nl_g8) {
                const __half* kp = kg + ((((size_t)bh * 4 + (jg8 & 3)) * 256 + (jg8 >> 2)) * 64);
#pragma unroll
                for (int d = 0; d < 16; d += 2) {
                    __half2 a = *(const __half2*)&Qs[(wq + g + 8) * KVS + t4 * 16 + d];
                    __half2 b = *(const __half2*)(kp + t4 * 16 + d);
                    d1 += __half2float(a.x) * __half2float(b.x)
                        + __half2float(a.y) * __half2float(b.y);
                }
            }
            d0 += __shfl_xor_sync(0xffffffffu, d0, 1);
            d0 += __shfl_xor_sync(0xffffffffu, d0, 2);
            d1 += __shfl_xor_sync(0xffffffffu, d1, 1);
            d1 += __shfl_xor_sync(0xffffffffu, d1, 2);
            sg[l]  = (l < nl_g)  ? d0 * 0.125f : -1e30f;
            sg8[l] = (l < nl_g8) ? d1 * 0.125f : -1e30f;
        }
        m_g  = fmaxf(fmaxf(sg[0], sg[1]), sg[2]);
        m_g8 = fmaxf(fmaxf(sg8[0], sg8[1]), sg8[2]);
        float p_g[3], p_g8[3];
        l_g = 0.f; l_g8 = 0.f;
#pragma unroll
        for (int l = 0; l < 3; l++) {
            p_g[l]  = (l < nl_g)  ? __expf(sg[l] - m_g)   : 0.f;
            p_g8[l] = (l < nl_g8) ? __expf(sg8[l] - m_g8) : 0.f;
            l_g += p_g[l]; l_g8 += p_g8[l];
        }
#pragma unroll
        for (int l = 0; l < 3; l++) {
            int jg = i_g - 1 - l, jg8 = i_g8 - 1 - l;
            if (l < nl_g) {
                const __half* vp = vg + ((((size_t)bh * 4 + (jg & 3)) * 256 + (jg >> 2)) * 64);
#pragma unroll
                for (int nt = 0; nt < 8; nt++) {
                    __half2 v2 = *(const __half2*)(vp + nt * 8 + t4 * 2);
                    oacc[nt][0] += p_g[l] * __half2float(v2.x);
                    oacc[nt][1] += p_g[l] * __half2float(v2.y);
                }
            }
            if (l < nl_g8) {
                const __half* vp = vg + ((((size_t)bh * 4 + (jg8 & 3)) * 256 + (jg8 >> 2)) * 64);
#pragma unroll
                for (int nt = 0; nt < 8; nt++) {
                    __half2 v2 = *(const __half2*)(vp + nt * 8 + t4 * 2);
                    oacc[nt][2] += p_g8[l] * __half2float(v2.x);
                    oacc[nt][3] += p_g8[l] * __half2float(v2.y);
                }
            }
        }
    }

    int buf = 0;
    for (int ut = 0; ut < ntiles; ut++) {
        CP_WAIT(0);
        __syncthreads();
        if (ut + 1 < ntiles) {
            stage_kv(buf ^ 1, ut + 1);
            CP_COMMIT();
        }

        float acc[8][4];
#pragma unroll
        for (int nt = 0; nt < 8; nt++)
#pragma unroll
            for (int c = 0; c < 4; c++) acc[nt][c] = 0.f;
#pragma unroll
        for (int ks = 0; ks < 4; ks++)
#pragma unroll
            for (int nb = 0; nb < 4; nb++) {
                uint32_t bh4[4];
                ldm_x4(bh4, &Kb[buf * 64 * KVS + (nb * 16 + bnrow) * KVS + ks * 16 + bkoff]);
                mma16816(acc[nb * 2 + 0], qf[ks], &bh4[0]);
                mma16816(acc[nb * 2 + 1], qf[ks], &bh4[2]);
            }

        if (ut == qt) {
            const int lim_g = wq + g, lim_g8 = wq + g + 8;
#pragma unroll
            for (int nt = 0; nt < 8; nt++) {
                int u0 = nt * 8 + t4 * 2;
                acc[nt][0] = (u0     <= lim_g)  ? acc[nt][0] * 0.125f : -1e30f;
                acc[nt][1] = (u0 + 1 <= lim_g)  ? acc[nt][1] * 0.125f : -1e30f;
                acc[nt][2] = (u0     <= lim_g8) ? acc[nt][2] * 0.125f : -1e30f;
                acc[nt][3] = (u0 + 1 <= lim_g8) ? acc[nt][3] * 0.125f : -1e30f;
            }
        } else {
#pragma unroll
            for (int nt = 0; nt < 8; nt++)
#pragma unroll
                for (int c = 0; c < 4; c++) acc[nt][c] *= 0.125f;
        }

        float tm_g = -1e30f, tm_g8 = -1e30f;
#pragma unroll
        for (int nt = 0; nt < 8; nt++) {
            tm_g  = fmaxf(tm_g,  fmaxf(acc[nt][0], acc[nt][1]));
            tm_g8 = fmaxf(tm_g8, fmaxf(acc[nt][2], acc[nt][3]));
        }
        tm_g  = fmaxf(tm_g,  __shfl_xor_sync(0xffffffffu, tm_g, 1));
        tm_g  = fmaxf(tm_g,  __shfl_xor_sync(0xffffffffu, tm_g, 2));
        tm_g8 = fmaxf(tm_g8, __shfl_xor_sync(0xffffffffu, tm_g8, 1));
        tm_g8 = fmaxf(tm_g8, __shfl_xor_sync(0xffffffffu, tm_g8, 2));

        float mn_g = fmaxf(m_g, tm_g), mn_g8 = fmaxf(m_g8, tm_g8);
        float al_g = __expf(m_g - mn_g), al_g8 = __expf(m_g8 - mn_g8);
        m_g = mn_g; m_g8 = mn_g8;

        float ps_g = 0.f, ps_g8 = 0.f;
#pragma unroll
        for (int nt = 0; nt < 8; nt++) {
            float p0 = __expf(acc[nt][0] - mn_g);
            float p1 = __expf(acc[nt][1] - mn_g);
            float p2 = __expf(acc[nt][2] - mn_g8);
            float p3 = __expf(acc[nt][3] - mn_g8);
            acc[nt][0] = p0; acc[nt][1] = p1; acc[nt][2] = p2; acc[nt][3] = p3;
            ps_g += p0 + p1; ps_g8 += p2 + p3;
        }
        ps_g  += __shfl_xor_sync(0xffffffffu, ps_g, 1);
        ps_g  += __shfl_xor_sync(0xffffffffu, ps_g, 2);
        ps_g8 += __shfl_xor_sync(0xffffffffu, ps_g8, 1);
        ps_g8 += __shfl_xor_sync(0xffffffffu, ps_g8, 2);
        l_g = l_g * al_g + ps_g;
        l_g8 = l_g8 * al_g8 + ps_g8;
#pragma unroll
        for (int nt = 0; nt < 8; nt++) {
            oacc[nt][0] *= al_g;  oacc[nt][1] *= al_g;
            oacc[nt][2] *= al_g8; oacc[nt][3] *= al_g8;
        }

#pragma unroll
        for (int ks = 0; ks < 4; ks++) {
            uint32_t pa[4];
            pa[0] = packh2(acc[2 * ks][0],     acc[2 * ks][1]);
            pa[1] = packh2(acc[2 * ks][2],     acc[2 * ks][3]);
            pa[2] = packh2(acc[2 * ks + 1][0], acc[2 * ks + 1][1]);
            pa[3] = packh2(acc[2 * ks + 1][2], acc[2 * ks + 1][3]);
#pragma unroll
            for (int nb = 0; nb < 4; nb++) {
                uint32_t vh4[4];
                ldm_x4_t(vh4, &Vb[buf * 64 * KVS + (ks * 16 + lrow) * KVS + nb * 16 + lcol]);
                mma16816(oacc[nb * 2 + 0], pa, &vh4[0]);
                mma16816(oacc[nb * 2 + 1], pa, &vh4[2]);
            }
        }
        buf ^= 1;
    }

    __syncthreads();
    {
        float inv_g = 1.0f / l_g, inv_g8 = 1.0f / l_g8;
#pragma unroll
        for (int nt = 0; nt < 8; nt++) {
            *(__half2*)&Qs[(wq + g) * KVS + nt * 8 + t4 * 2] =
                __floats2half2_rn(oacc[nt][0] * inv_g, oacc[nt][1] * inv_g);
            *(__half2*)&Qs[(wq + g + 8) * KVS + nt * 8 + t4 * 2] =
                __floats2half2_rn(oacc[nt][2] * inv_g8, oacc[nt][3] * inv_g8);
        }
    }
    __syncthreads();
    {
        int bb = bh >> 4, h = bh & 15;
#pragma unroll
        for (int j = 0; j < 4; j++) {
            int c = tid + 128 * j, row = c >> 3, co = (c & 7) * 8;
            int i = 4 * (q0 + row) + r;
            *(uint4*)(out + ((size_t)(bb * 1024 + i)) * 1024 + h * 64 + co) =
                *(const uint4*)&Qs[row * KVS + co];
        }
    }
    __syncthreads();
}

__global__ void __launch_bounds__(128) attn_flash_kernel(
    const __half* __restrict__ qg, const __half* __restrict__ kg,
    const __half* __restrict__ vg, __half* __restrict__ out)
{
    __shared__ __half Qs[64 * KVS];
    __shared__ __half Kb[2 * 64 * KVS];
    __shared__ __half Vb[2 * 64 * KVS];

    const int p  = blockIdx.x >> 8;
    const int bh = (blockIdx.x & 255) >> 2;
    const int r  = blockIdx.x & 3;
    const int qtA = (p == 0) ? 3 : 2;
    const int qtB = (p == 0) ? 0 : 1;

    attn_body(qg, kg, vg, out, Qs, Kb, Vb, bh, r, qtA);
    attn_body(qg, kg, vg, out, Qs, Kb, Vb, bh, r, qtB);
}

// ---------------------------------------------------------------------------
extern "C" void kernel_launch(void* const* d_in, const int* in_sizes, int n_in,
                              void* d_out, int out_size)
{
    const float* Q  = (const float*)d_in[0];
    const float* K  = (const float*)d_in[1];
    const float* V  = (const float*)d_in[2];
    const float* Wq = (const float*)d_in[3];
    const float* bq = (const float*)d_in[4];
    const float* Wk = (const float*)d_in[5];
    const float* bk = (const float*)d_in[6];
    const float* Wv = (const float*)d_in[7];
    const float* bv = (const float*)d_in[8];
    const float* Wo = (const float*)d_in[9];
    const float* bo = (const float*)d_in[10];
    float* out = (float*)d_out;

    __half *pqin, *pkin, *pvin, *pw, *pq, *pk, *pv, *pah;
    cudaGetSymbolAddress((void**)&pqin, g_qin);
    cudaGetSymbolAddress((void**)&pkin, g_kin);
    cudaGetSymbolAddress((void**)&pvin, g_vin);
    cudaGetSymbolAddress((void**)&pw, g_w);
    cudaGetSymbolAddress((void**)&pq, g_q);
    cudaGetSymbolAddress((void**)&pk, g_k);
    cudaGetSymbolAddress((void**)&pv, g_v);
    cudaGetSymbolAddress((void**)&pah, g_attn);

    cudaFuncSetAttribute(gemm_qkv_kernel,
                         cudaFuncAttributeMaxDynamicSharedMemorySize, GEMM_SMEM);
    cudaFuncSetAttribute(gemm_o_kernel,
                         cudaFuncAttributeMaxDynamicSharedMemorySize, GEMM_SMEM);

    convall_kernel<<<4096, 256>>>(Q, K, V, Wq, Wk, Wv, Wo, pqin, pkin, pvin, pw);

    gemm_qkv_kernel<<<dim3(8, 32, 3), 256, GEMM_SMEM>>>(
        pqin, pkin, pvin, pw, bq, bk, bv, pq, pk, pv);

    attn_flash_kernel<<<512, 128>>>(pq, pk, pv, pah);

    gemm_o_kernel<<<dim3(8, 32), 256, GEMM_SMEM>>>(
        pah, pw + 3 * (size_t)DD * DD, bo, out);
}

// round 14
// speedup vs baseline: 1.3207x; 1.3207x over previous
#include <cuda_runtime.h>
#include <cuda_fp16.h>
#include <cstdint>

#define BB 4
#define SS 1024
#define DD 1024
#define HH 16
#define DK 64
#define NEL (BB * HH * SS * DK)   // 4M

// Scratch (__device__ globals)
__device__ __half g_qin[NEL], g_kin[NEL], g_vin[NEL];   // fp16 input copies [B,S,D]
__device__ __half g_w[4 * DD * DD];                     // fp16 weights [k][n] (4 mats)
__device__ __half g_q[NEL];          // [bh][s][d]
__device__ __half g_k[NEL];          // [bh][r][u][d]
__device__ __half g_v[NEL];          // [bh][r][u][d]
__device__ __half g_attn[BB * SS * DD];                 // fp16 attention out [B,S,D]

// ---------------------------------------------------------------------------
__device__ __forceinline__ unsigned saddr(const void* p) {
    return (unsigned)__cvta_generic_to_shared(p);
}
__device__ __forceinline__ void ldm_x4(uint32_t* r, const void* p) {
    asm volatile("ldmatrix.sync.aligned.m8n8.x4.shared.b16 {%0,%1,%2,%3}, [%4];"
        : "=r"(r[0]), "=r"(r[1]), "=r"(r[2]), "=r"(r[3]) : "r"(saddr(p)));
}
__device__ __forceinline__ void ldm_x4_t(uint32_t* r, const void* p) {
    asm volatile("ldmatrix.sync.aligned.m8n8.x4.trans.shared.b16 {%0,%1,%2,%3}, [%4];"
        : "=r"(r[0]), "=r"(r[1]), "=r"(r[2]), "=r"(r[3]) : "r"(saddr(p)));
}
__device__ __forceinline__ void mma16816(float* c, const uint32_t* a, const uint32_t* b) {
    asm volatile("mma.sync.aligned.m16n8k16.row.col.f32.f16.f16.f32 "
        "{%0,%1,%2,%3},{%4,%5,%6,%7},{%8,%9},{%0,%1,%2,%3};"
        : "+f"(c[0]), "+f"(c[1]), "+f"(c[2]), "+f"(c[3])
        : "r"(a[0]), "r"(a[1]), "r"(a[2]), "r"(a[3]), "r"(b[0]), "r"(b[1]));
}
__device__ __forceinline__ void cp_async16(void* s, const void* g) {
    asm volatile("cp.async.cg.shared.global [%0], [%1], 16;"
        :: "r"(saddr(s)), "l"(g));
}
#define CP_COMMIT() asm volatile("cp.async.commit_group;" ::: "memory")
#define CP_WAIT(n)  asm volatile("cp.async.wait_group %0;" :: "n"(n) : "memory")

__device__ __forceinline__ uint32_t packh2(float a, float b) {
    __half2 p = __floats2half2_rn(a, b);
    return *(uint32_t*)&p;
}

// ---------------------------------------------------------------------------
// Fused prep: all fp32->fp16 in ONE launch, 4 float4 per thread (MLP=4).
// ---------------------------------------------------------------------------
__global__ void __launch_bounds__(256) convall_kernel(
    const float* __restrict__ Q, const float* __restrict__ K,
    const float* __restrict__ V,
    const float* __restrict__ W0, const float* __restrict__ W1,
    const float* __restrict__ W2, const float* __restrict__ W3,
    __half* __restrict__ dq, __half* __restrict__ dk, __half* __restrict__ dv,
    __half* __restrict__ dw)
{
    int b = blockIdx.x;
    const float* src;
    __half* dst;
    int lb;
    if (b < 1024)       { src = Q; dst = dq; lb = b; }
    else if (b < 2048)  { src = K; dst = dk; lb = b - 1024; }
    else if (b < 3072)  { src = V; dst = dv; lb = b - 2048; }
    else {
        int wb = b - 3072;
        int wz = wb >> 8;
        src = (wz == 0) ? W0 : (wz == 1) ? W1 : (wz == 2) ? W2 : W3;
        dst = dw + (size_t)wz * DD * DD;
        lb = wb & 255;
    }
    float4 v[4];
    size_t base = (size_t)lb * 1024 + threadIdx.x;
#pragma unroll
    for (int it = 0; it < 4; it++)
        v[it] = *(const float4*)(src + (base + it * 256) * 4);
#pragma unroll
    for (int it = 0; it < 4; it++) {
        uint2 u; u.x = packh2(v[it].x, v[it].y); u.y = packh2(v[it].z, v[it].w);
        *(uint2*)(dst + (base + it * 256) * 4) = u;
    }
}

// ---------------------------------------------------------------------------
// fp16 GEMM body (R12 winner + WPAD conflict fix): BK=64, 3-stage cp.async,
// 256 thr, 64x32 warp tiles. WPAD=136 -> 272B W row stride, conflict-free
// ldmatrix (288B was 2-way conflicted).
// ---------------------------------------------------------------------------
#define APAD 72              // 144B row stride (conflict-free)
#define WPAD 136             // 272B row stride (conflict-free)
#define A_SZ (128 * APAD)
#define W_SZ (64 * WPAD)
#define STAGES 3
#define GEMM_SMEM (STAGES * (A_SZ + W_SZ) * 2)   // 107,520 bytes

__device__ __forceinline__ void store2(
    float* __restrict__ C, __half* __restrict__ O, int mode,
    int m, int n, float v0, float v1)
{
    if (mode == 0) {
        *(float2*)(C + (size_t)m * 1024 + n) = make_float2(v0, v1);
        return;
    }
    int b = m >> 10, s = m & 1023, h = n >> 6, d = n & 63;
    size_t idx;
    if (mode == 1) idx = (((size_t)(b * 16 + h)) * 1024 + s) * 64 + d;
    else           idx = ((((size_t)(b * 16 + h)) * 4 + (s & 3)) * 256 + (s >> 2)) * 64 + d;
    __half2 p = __floats2half2_rn(v0, v1);
    *(__half2*)(O + idx) = p;
}

__device__ __forceinline__ void gemm_body(
    const __half* __restrict__ A, const __half* __restrict__ Wm,
    const float* __restrict__ bias, float* __restrict__ C,
    __half* __restrict__ O, int mode, __half* smem)
{
    __half* sA = smem;                       // [STAGES][128][APAD]
    __half* sW = smem + STAGES * A_SZ;       // [STAGES][64][WPAD]

    const int tid = threadIdx.x;
    const int bm = blockIdx.y * 128, bn = blockIdx.x * 128;
    const int w = tid >> 5, lane = tid & 31;
    const int wm = (w & 1) * 64, wn = (w >> 1) * 32;
    const int lrow = lane & 15, lcol = (lane >> 4) << 3;

    float acc[4][4][4];
#pragma unroll
    for (int i = 0; i < 4; i++)
#pragma unroll
        for (int j = 0; j < 4; j++)
#pragma unroll
            for (int t = 0; t < 4; t++) acc[i][j][t] = 0.f;

    auto stage = [&](int buf, int k0) {
#pragma unroll
        for (int j = 0; j < 4; j++) {
            int c = tid + 256 * j;
            int arow = c >> 3, aco = (c & 7) * 8;
            cp_async16(&sA[buf * A_SZ + arow * APAD + aco],
                       A + (size_t)(bm + arow) * 1024 + k0 + aco);
            int wrow = c >> 4, wco = (c & 15) * 8;
            cp_async16(&sW[buf * W_SZ + wrow * WPAD + wco],
                       Wm + (size_t)(k0 + wrow) * 1024 + bn + wco);
        }
    };

#pragma unroll
    for (int s = 0; s < STAGES - 1; s++) {
        stage(s, s * 64);
        CP_COMMIT();
    }

    for (int kt = 0; kt < 16; kt++) {
        CP_WAIT(STAGES - 2);
        __syncthreads();

        int nk = kt + STAGES - 1;
        if (nk < 16) stage(nk % STAGES, nk * 64);
        CP_COMMIT();

        const __half* cA = sA + (kt % STAGES) * A_SZ;
        const __half* cW = sW + (kt % STAGES) * W_SZ;

#pragma unroll
        for (int kk = 0; kk < 64; kk += 16) {
            uint32_t a[4][4], b_[2][4];
#pragma unroll
            for (int mt = 0; mt < 4; mt++)
                ldm_x4(a[mt], &cA[(wm + mt * 16 + lrow) * APAD + kk + lcol]);
#pragma unroll
            for (int np = 0; np < 2; np++)
                ldm_x4_t(b_[np], &cW[(kk + lrow) * WPAD + wn + np * 16 + lcol]);
#pragma unroll
            for (int mt = 0; mt < 4; mt++)
#pragma unroll
                for (int nt = 0; nt < 4; nt++)
                    mma16816(acc[mt][nt], a[mt], &b_[nt >> 1][(nt & 1) * 2]);
        }
    }

    const int g = lane >> 2, t4 = lane & 3;
#pragma unroll
    for (int mt = 0; mt < 4; mt++)
#pragma unroll
        for (int nt = 0; nt < 4; nt++) {
            int m0 = bm + wm + mt * 16 + g;
            int n0 = bn + wn + nt * 8 + t4 * 2;
            float b0 = __ldg(bias + n0), b1 = __ldg(bias + n0 + 1);
            store2(C, O, mode, m0,     n0, acc[mt][nt][0] + b0, acc[mt][nt][1] + b1);
            store2(C, O, mode, m0 + 8, n0, acc[mt][nt][2] + b0, acc[mt][nt][3] + b1);
        }
}

__global__ void __launch_bounds__(256) gemm_qkv_kernel(
    const __half* __restrict__ Aq, const __half* __restrict__ Ak,
    const __half* __restrict__ Av, const __half* __restrict__ Wall,
    const float* __restrict__ bq, const float* __restrict__ bk,
    const float* __restrict__ bv,
    __half* __restrict__ Oq, __half* __restrict__ Ok, __half* __restrict__ Ov)
{
    extern __shared__ __half smem[];
    int z = blockIdx.z;
    const __half* A = (z == 0) ? Aq : (z == 1) ? Ak : Av;
    const float* bias = (z == 0) ? bq : (z == 1) ? bk : bv;
    __half* O = (z == 0) ? Oq : (z == 1) ? Ok : Ov;
    gemm_body(A, Wall + (size_t)z * DD * DD, bias, nullptr, O,
              (z == 0) ? 1 : 2, smem);
}

__global__ void __launch_bounds__(256) gemm_o_kernel(
    const __half* __restrict__ A, const __half* __restrict__ Wm,
    const float* __restrict__ bias, float* __restrict__ C)
{
    extern __shared__ __half smem[];
    gemm_body(A, Wm, bias, C, nullptr, 0, smem);
}

// ---------------------------------------------------------------------------
// Flash attention body (R10-proven inner code), pair-balanced blocks.
// ---------------------------------------------------------------------------
#define KVS 72

__device__ __forceinline__ void attn_body(
    const __half* __restrict__ qg, const __half* __restrict__ kg,
    const __half* __restrict__ vg, __half* __restrict__ out,
    __half* Qs, __half* Kb, __half* Vb, int bh, int r, int qt)
{
    const int tid = threadIdx.x, lane = tid & 31, w = tid >> 5;
    const int q0 = qt * 64;
    const int ntiles = qt + 1;

    const int wq = w * 16;
    const int g = lane >> 2, t4 = lane & 3;
    const int lrow = lane & 15, lcol = (lane >> 4) << 3;
    const int bnrow = ((lane >> 4) << 3) + (lane & 7);
    const int bkoff = ((lane >> 3) & 1) << 3;

    const __half* kbase = kg + (((size_t)bh * 4 + r) * 256) * 64;
    const __half* vbase = vg + (((size_t)bh * 4 + r) * 256) * 64;

#pragma unroll
    for (int j = 0; j < 4; j++) {
        int c = tid + 128 * j, row = c >> 3, co = (c & 7) * 8;
        int i = 4 * (q0 + row) + r;
        *(uint4*)&Qs[row * KVS + co] =
            *(const uint4*)(qg + ((size_t)bh * 1024 + i) * 64 + co);
    }
    __syncthreads();

    auto stage_kv = [&](int buf, int ut) {
#pragma unroll
        for (int j = 0; j < 4; j++) {
            int c = tid + 128 * j, row = c >> 3, co = (c & 7) * 8;
            cp_async16(&Kb[buf * 64 * KVS + row * KVS + co],
                       kbase + (size_t)(ut * 64 + row) * 64 + co);
            cp_async16(&Vb[buf * 64 * KVS + row * KVS + co],
                       vbase + (size_t)(ut * 64 + row) * 64 + co);
        }
    };
    stage_kv(0, 0);
    CP_COMMIT();

    uint32_t qf[4][4];
#pragma unroll
    for (int ks = 0; ks < 4; ks++)
        ldm_x4(qf[ks], &Qs[(wq + lrow) * KVS + ks * 16 + lcol]);

    const int i_g  = 4 * (q0 + wq + g) + r;
    const int i_g8 = i_g + 32;
    float m_g, m_g8, l_g, l_g8;
    float oacc[8][4];
#pragma unroll
    for (int nt = 0; nt < 8; nt++)
#pragma unroll
        for (int c = 0; c < 4; c++) oacc[nt][c] = 0.f;
    {
        float sg[3], sg8[3];
        const int nl_g = min(i_g, 3), nl_g8 = min(i_g8, 3);
#pragma unroll
        for (int l = 0; l < 3; l++) {
            float d0 = 0.f, d1 = 0.f;
            int jg = i_g - 1 - l, jg8 = i_g8 - 1 - l;
            if (l < nl_g) {
                const __half* kp = kg + ((((size_t)bh * 4 + (jg & 3)) * 256 + (jg >> 2)) * 64);
#pragma unroll
                for (int d = 0; d < 16; d += 2) {
                    __half2 a = *(const __half2*)&Qs[(wq + g) * KVS + t4 * 16 + d];
                    __half2 b = *(const __half2*)(kp + t4 * 16 + d);
                    d0 += __half2float(a.x) * __half2float(b.x)
                        + __half2float(a.y) * __half2float(b.y);
                }
            }
            if (l < nl_g8) {
                const __half* kp = kg + ((((size_t)bh * 4 + (jg8 & 3)) * 256 + (jg8 >> 2)) * 64);
#pragma unroll
                for (int d = 0; d < 16; d += 2) {
                    __half2 a = *(const __half2*)&Qs[(wq + g + 8) * KVS + t4 * 16 + d];
                    __half2 b = *(const __half2*)(kp + t4 * 16 + d);
                    d1 += __half2float(a.x) * __half2float(b.x)
                        + __half2float(a.y) * __half2float(b.y);
                }
            }
            d0 += __shfl_xor_sync(0xffffffffu, d0, 1);
            d0 += __shfl_xor_sync(0xffffffffu, d0, 2);
            d1 += __shfl_xor_sync(0xffffffffu, d1, 1);
            d1 += __shfl_xor_sync(0xffffffffu, d1, 2);
            sg[l]  = (l < nl_g)  ? d0 * 0.125f : -1e30f;
            sg8[l] = (l < nl_g8) ? d1 * 0.125f : -1e30f;
        }
        m_g  = fmaxf(fmaxf(sg[0], sg[1]), sg[2]);
        m_g8 = fmaxf(fmaxf(sg8[0], sg8[1]), sg8[2]);
        float p_g[3], p_g8[3];
        l_g = 0.f; l_g8 = 0.f;
#pragma unroll
        for (int l = 0; l < 3; l++) {
            p_g[l]  = (l < nl_g)  ? __expf(sg[l] - m_g)   : 0.f;
            p_g8[l] = (l < nl_g8) ? __expf(sg8[l] - m_g8) : 0.f;
            l_g += p_g[l]; l_g8 += p_g8[l];
        }
#pragma unroll
        for (int l = 0; l < 3; l++) {
            int jg = i_g - 1 - l, jg8 = i_g8 - 1 - l;
            if (l < nl_g) {
                const __half* vp = vg + ((((size_t)bh * 4 + (jg & 3)) * 256 + (jg >> 2)) * 64);
#pragma unroll
                for (int nt = 0; nt < 8; nt++) {
                    __half2 v2 = *(const __half2*)(vp + nt * 8 + t4 * 2);
                    oacc[nt][0] += p_g[l] * __half2float(v2.x);
                    oacc[nt][1] += p_g[l] * __half2float(v2.y);
                }
            }
            if (l < nl_g8) {
                const __half* vp = vg + ((((size_t)bh * 4 + (jg8 & 3)) * 256 + (jg8 >> 2)) * 64);
#pragma unroll
                for (int nt = 0; nt < 8; nt++) {
                    __half2 v2 = *(const __half2*)(vp + nt * 8 + t4 * 2);
                    oacc[nt][2] += p_g8[l] * __half2float(v2.x);
                    oacc[nt][3] += p_g8[l] * __half2float(v2.y);
                }
            }
        }
    }

    int buf = 0;
    for (int ut = 0; ut < ntiles; ut++) {
        CP_WAIT(0);
        __syncthreads();
        if (ut + 1 < ntiles) {
            stage_kv(buf ^ 1, ut + 1);
            CP_COMMIT();
        }

        float acc[8][4];
#pragma unroll
        for (int nt = 0; nt < 8; nt++)
#pragma unroll
            for (int c = 0; c < 4; c++) acc[nt][c] = 0.f;
#pragma unroll
        for (int ks = 0; ks < 4; ks++)
#pragma unroll
            for (int nb = 0; nb < 4; nb++) {
                uint32_t bh4[4];
                ldm_x4(bh4, &Kb[buf * 64 * KVS + (nb * 16 + bnrow) * KVS + ks * 16 + bkoff]);
                mma16816(acc[nb * 2 + 0], qf[ks], &bh4[0]);
                mma16816(acc[nb * 2 + 1], qf[ks], &bh4[2]);
            }

        if (ut == qt) {
            const int lim_g = wq + g, lim_g8 = wq + g + 8;
#pragma unroll
            for (int nt = 0; nt < 8; nt++) {
                int u0 = nt * 8 + t4 * 2;
                acc[nt][0] = (u0     <= lim_g)  ? acc[nt][0] * 0.125f : -1e30f;
                acc[nt][1] = (u0 + 1 <= lim_g)  ? acc[nt][1] * 0.125f : -1e30f;
                acc[nt][2] = (u0     <= lim_g8) ? acc[nt][2] * 0.125f : -1e30f;
                acc[nt][3] = (u0 + 1 <= lim_g8) ? acc[nt][3] * 0.125f : -1e30f;
            }
        } else {
#pragma unroll
            for (int nt = 0; nt < 8; nt++)
#pragma unroll
                for (int c = 0; c < 4; c++) acc[nt][c] *= 0.125f;
        }

        float tm_g = -1e30f, tm_g8 = -1e30f;
#pragma unroll
        for (int nt = 0; nt < 8; nt++) {
            tm_g  = fmaxf(tm_g,  fmaxf(acc[nt][0], acc[nt][1]));
            tm_g8 = fmaxf(tm_g8, fmaxf(acc[nt][2], acc[nt][3]));
        }
        tm_g  = fmaxf(tm_g,  __shfl_xor_sync(0xffffffffu, tm_g, 1));
        tm_g  = fmaxf(tm_g,  __shfl_xor_sync(0xffffffffu, tm_g, 2));
        tm_g8 = fmaxf(tm_g8, __shfl_xor_sync(0xffffffffu, tm_g8, 1));
        tm_g8 = fmaxf(tm_g8, __shfl_xor_sync(0xffffffffu, tm_g8, 2));

        float mn_g = fmaxf(m_g, tm_g), mn_g8 = fmaxf(m_g8, tm_g8);
        float al_g = __expf(m_g - mn_g), al_g8 = __expf(m_g8 - mn_g8);
        m_g = mn_g; m_g8 = mn_g8;

        float ps_g = 0.f, ps_g8 = 0.f;
#pragma unroll
        for (int nt = 0; nt < 8; nt++) {
            float p0 = __expf(acc[nt][0] - mn_g);
            float p1 = __expf(acc[nt][1] - mn_g);
            float p2 = __expf(acc[nt][2] - mn_g8);
            float p3 = __expf(acc[nt][3] - mn_g8);
            acc[nt][0] = p0; acc[nt][1] = p1; acc[nt][2] = p2; acc[nt][3] = p3;
            ps_g += p0 + p1; ps_g8 += p2 + p3;
        }
        ps_g  += __shfl_xor_sync(0xffffffffu, ps_g, 1);
        ps_g  += __shfl_xor_sync(0xffffffffu, ps_g, 2);
        ps_g8 += __shfl_xor_sync(0xffffffffu, ps_g8, 1);
        ps_g8 += __shfl_xor_sync(0xffffffffu, ps_g8, 2);
        l_g = l_g * al_g + ps_g;
        l_g8 = l_g8 * al_g8 + ps_g8;
#pragma unroll
        for (int nt = 0; nt < 8; nt++) {
            oacc[nt][0] *= al_g;  oacc[nt][1] *= al_g;
            oacc[nt][2] *= al_g8; oacc[nt][3] *= al_g8;
        }

#pragma unroll
        for (int ks = 0; ks < 4; ks++) {
            uint32_t pa[4];
            pa[0] = packh2(acc[2 * ks][0],     acc[2 * ks][1]);
            pa[1] = packh2(acc[2 * ks][2],     acc[2 * ks][3]);
            pa[2] = packh2(acc[2 * ks + 1][0], acc[2 * ks + 1][1]);
            pa[3] = packh2(acc[2 * ks + 1][2], acc[2 * ks + 1][3]);
#pragma unroll
            for (int nb = 0; nb < 4; nb++) {
                uint32_t vh4[4];
                ldm_x4_t(vh4, &Vb[buf * 64 * KVS + (ks * 16 + lrow) * KVS + nb * 16 + lcol]);
                mma16816(oacc[nb * 2 + 0], pa, &vh4[0]);
                mma16816(oacc[nb * 2 + 1], pa, &vh4[2]);
            }
        }
        buf ^= 1;
    }

    __syncthreads();
    {
        float inv_g = 1.0f / l_g, inv_g8 = 1.0f / l_g8;
#pragma unroll
        for (int nt = 0; nt < 8; nt++) {
            *(__half2*)&Qs[(wq + g) * KVS + nt * 8 + t4 * 2] =
                __floats2half2_rn(oacc[nt][0] * inv_g, oacc[nt][1] * inv_g);
            *(__half2*)&Qs[(wq + g + 8) * KVS + nt * 8 + t4 * 2] =
                __floats2half2_rn(oacc[nt][2] * inv_g8, oacc[nt][3] * inv_g8);
        }
    }
    __syncthreads();
    {
        int bb = bh >> 4, h = bh & 15;
#pragma unroll
        for (int j = 0; j < 4; j++) {
            int c = tid + 128 * j, row = c >> 3, co = (c & 7) * 8;
            int i = 4 * (q0 + row) + r;
            *(uint4*)(out + ((size_t)(bb * 1024 + i)) * 1024 + h * 64 + co) =
                *(const uint4*)&Qs[row * KVS + co];
        }
    }
    __syncthreads();
}

__global__ void __launch_bounds__(128) attn_flash_kernel(
    const __half* __restrict__ qg, const __half* __restrict__ kg,
    const __half* __restrict__ vg, __half* __restrict__ out)
{
    __shared__ __half Qs[64 * KVS];
    __shared__ __half Kb[2 * 64 * KVS];
    __shared__ __half Vb[2 * 64 * KVS];

    const int p  = blockIdx.x >> 8;
    const int bh = (blockIdx.x & 255) >> 2;
    const int r  = blockIdx.x & 3;
    const int qtA = (p == 0) ? 3 : 2;
    const int qtB = (p == 0) ? 0 : 1;

    attn_body(qg, kg, vg, out, Qs, Kb, Vb, bh, r, qtA);
    attn_body(qg, kg, vg, out, Qs, Kb, Vb, bh, r, qtB);
}

// ---------------------------------------------------------------------------
extern "C" void kernel_launch(void* const* d_in, const int* in_sizes, int n_in,
                              void* d_out, int out_size)
{
    const float* Q  = (const float*)d_in[0];
    const float* K  = (const float*)d_in[1];
    const float* V  = (const float*)d_in[2];
    const float* Wq = (const float*)d_in[3];
    const float* bq = (const float*)d_in[4];
    const float* Wk = (const float*)d_in[5];
    const float* bk = (const float*)d_in[6];
    const float* Wv = (const float*)d_in[7];
    const float* bv = (const float*)d_in[8];
    const float* Wo = (const float*)d_in[9];
    const float* bo = (const float*)d_in[10];
    float* out = (float*)d_out;

    __half *pqin, *pkin, *pvin, *pw, *pq, *pk, *pv, *pah;
    cudaGetSymbolAddress((void**)&pqin, g_qin);
    cudaGetSymbolAddress((void**)&pkin, g_kin);
    cudaGetSymbolAddress((void**)&pvin, g_vin);
    cudaGetSymbolAddress((void**)&pw, g_w);
    cudaGetSymbolAddress((void**)&pq, g_q);
    cudaGetSymbolAddress((void**)&pk, g_k);
    cudaGetSymbolAddress((void**)&pv, g_v);
    cudaGetSymbolAddress((void**)&pah, g_attn);

    cudaFuncSetAttribute(gemm_qkv_kernel,
                         cudaFuncAttributeMaxDynamicSharedMemorySize, GEMM_SMEM);
    cudaFuncSetAttribute(gemm_o_kernel,
                         cudaFuncAttributeMaxDynamicSharedMemorySize, GEMM_SMEM);

    convall_kernel<<<4096, 256>>>(Q, K, V, Wq, Wk, Wv, Wo, pqin, pkin, pvin, pw);

    gemm_qkv_kernel<<<dim3(8, 32, 3), 256, GEMM_SMEM>>>(
        pqin, pkin, pvin, pw, bq, bk, bv, pq, pk, pv);

    attn_flash_kernel<<<512, 128>>>(pq, pk, pv, pah);

    gemm_o_kernel<<<dim3(8, 32), 256, GEMM_SMEM>>>(
        pah, pw + 3 * (size_t)DD * DD, bo, out);
}

// round 15
// speedup vs baseline: 1.3284x; 1.0058x over previous
#include <cuda_runtime.h>
#include <cuda_fp16.h>
#include <cstdint>

#define BB 4
#define SS 1024
#define DD 1024
#define HH 16
#define DK 64
#define NEL (BB * HH * SS * DK)   // 4M

// Scratch (__device__ globals)
__device__ __half g_qin[NEL], g_kin[NEL], g_vin[NEL];   // fp16 input copies [B,S,D]
__device__ __half g_w[4 * DD * DD];                     // fp16 weights [k][n] (4 mats)
__device__ __half g_q[NEL];          // [bh][s][d]
__device__ __half g_k[NEL];          // [bh][r][u][d]
__device__ __half g_v[NEL];          // [bh][r][u][d]
__device__ __half g_attn[BB * SS * DD];                 // fp16 attention out [B,S,D]

// 0.125 * log2(e): base-2 softmax domain
#define SC 0.18033688011112042f

// ---------------------------------------------------------------------------
__device__ __forceinline__ unsigned saddr(const void* p) {
    return (unsigned)__cvta_generic_to_shared(p);
}
__device__ __forceinline__ void ldm_x4(uint32_t* r, const void* p) {
    asm volatile("ldmatrix.sync.aligned.m8n8.x4.shared.b16 {%0,%1,%2,%3}, [%4];"
        : "=r"(r[0]), "=r"(r[1]), "=r"(r[2]), "=r"(r[3]) : "r"(saddr(p)));
}
__device__ __forceinline__ void ldm_x4_t(uint32_t* r, const void* p) {
    asm volatile("ldmatrix.sync.aligned.m8n8.x4.trans.shared.b16 {%0,%1,%2,%3}, [%4];"
        : "=r"(r[0]), "=r"(r[1]), "=r"(r[2]), "=r"(r[3]) : "r"(saddr(p)));
}
__device__ __forceinline__ void mma16816(float* c, const uint32_t* a, const uint32_t* b) {
    asm volatile("mma.sync.aligned.m16n8k16.row.col.f32.f16.f16.f32 "
        "{%0,%1,%2,%3},{%4,%5,%6,%7},{%8,%9},{%0,%1,%2,%3};"
        : "+f"(c[0]), "+f"(c[1]), "+f"(c[2]), "+f"(c[3])
        : "r"(a[0]), "r"(a[1]), "r"(a[2]), "r"(a[3]), "r"(b[0]), "r"(b[1]));
}
__device__ __forceinline__ void cp_async16(void* s, const void* g) {
    asm volatile("cp.async.cg.shared.global [%0], [%1], 16;"
        :: "r"(saddr(s)), "l"(g));
}
#define CP_COMMIT() asm volatile("cp.async.commit_group;" ::: "memory")
#define CP_WAIT(n)  asm volatile("cp.async.wait_group %0;" :: "n"(n) : "memory")

__device__ __forceinline__ uint32_t packh2(float a, float b) {
    __half2 p = __floats2half2_rn(a, b);
    return *(uint32_t*)&p;
}
__device__ __forceinline__ float ex2f(float x) {
    float y;
    asm("ex2.approx.f32 %0, %1;" : "=f"(y) : "f"(x));
    return y;
}
// 2^a, 2^b as packed fp16 pair (ONE MUFU op for two exponentials)
__device__ __forceinline__ uint32_t ex2_h2(float a, float b) {
    __half2 h = __floats2half2_rn(a, b);
    uint32_t u = *(uint32_t*)&h, r;
    asm("ex2.approx.f16x2 %0, %1;" : "=r"(r) : "r"(u));
    return r;
}
__device__ __forceinline__ float sum_h2(uint32_t u) {
    __half2 h = *(__half2*)&u;
    return __half2float(h.x) + __half2float(h.y);
}

// ---------------------------------------------------------------------------
// Fused prep: all fp32->fp16 in ONE launch, 4 float4 per thread (MLP=4).
// ---------------------------------------------------------------------------
__global__ void __launch_bounds__(256) convall_kernel(
    const float* __restrict__ Q, const float* __restrict__ K,
    const float* __restrict__ V,
    const float* __restrict__ W0, const float* __restrict__ W1,
    const float* __restrict__ W2, const float* __restrict__ W3,
    __half* __restrict__ dq, __half* __restrict__ dk, __half* __restrict__ dv,
    __half* __restrict__ dw)
{
    int b = blockIdx.x;
    const float* src;
    __half* dst;
    int lb;
    if (b < 1024)       { src = Q; dst = dq; lb = b; }
    else if (b < 2048)  { src = K; dst = dk; lb = b - 1024; }
    else if (b < 3072)  { src = V; dst = dv; lb = b - 2048; }
    else {
        int wb = b - 3072;
        int wz = wb >> 8;
        src = (wz == 0) ? W0 : (wz == 1) ? W1 : (wz == 2) ? W2 : W3;
        dst = dw + (size_t)wz * DD * DD;
        lb = wb & 255;
    }
    float4 v[4];
    size_t base = (size_t)lb * 1024 + threadIdx.x;
#pragma unroll
    for (int it = 0; it < 4; it++)
        v[it] = *(const float4*)(src + (base + it * 256) * 4);
#pragma unroll
    for (int it = 0; it < 4; it++) {
        uint2 u; u.x = packh2(v[it].x, v[it].y); u.y = packh2(v[it].z, v[it].w);
        *(uint2*)(dst + (base + it * 256) * 4) = u;
    }
}

// ---------------------------------------------------------------------------
// fp16 GEMM body (R14 winner, frozen): BK=64, 3-stage cp.async, 256 thr,
// 64x32 warp tiles, APAD=72 / WPAD=136 conflict-free.
// ---------------------------------------------------------------------------
#define APAD 72
#define WPAD 136
#define A_SZ (128 * APAD)
#define W_SZ (64 * WPAD)
#define STAGES 3
#define GEMM_SMEM (STAGES * (A_SZ + W_SZ) * 2)   // 107,520 bytes

__device__ __forceinline__ void store2(
    float* __restrict__ C, __half* __restrict__ O, int mode,
    int m, int n, float v0, float v1)
{
    if (mode == 0) {
        *(float2*)(C + (size_t)m * 1024 + n) = make_float2(v0, v1);
        return;
    }
    int b = m >> 10, s = m & 1023, h = n >> 6, d = n & 63;
    size_t idx;
    if (mode == 1) idx = (((size_t)(b * 16 + h)) * 1024 + s) * 64 + d;
    else           idx = ((((size_t)(b * 16 + h)) * 4 + (s & 3)) * 256 + (s >> 2)) * 64 + d;
    __half2 p = __floats2half2_rn(v0, v1);
    *(__half2*)(O + idx) = p;
}

__device__ __forceinline__ void gemm_body(
    const __half* __restrict__ A, const __half* __restrict__ Wm,
    const float* __restrict__ bias, float* __restrict__ C,
    __half* __restrict__ O, int mode, __half* smem)
{
    __half* sA = smem;                       // [STAGES][128][APAD]
    __half* sW = smem + STAGES * A_SZ;       // [STAGES][64][WPAD]

    const int tid = threadIdx.x;
    const int bm = blockIdx.y * 128, bn = blockIdx.x * 128;
    const int w = tid >> 5, lane = tid & 31;
    const int wm = (w & 1) * 64, wn = (w >> 1) * 32;
    const int lrow = lane & 15, lcol = (lane >> 4) << 3;

    float acc[4][4][4];
#pragma unroll
    for (int i = 0; i < 4; i++)
#pragma unroll
        for (int j = 0; j < 4; j++)
#pragma unroll
            for (int t = 0; t < 4; t++) acc[i][j][t] = 0.f;

    auto stage = [&](int buf, int k0) {
#pragma unroll
        for (int j = 0; j < 4; j++) {
            int c = tid + 256 * j;
            int arow = c >> 3, aco = (c & 7) * 8;
            cp_async16(&sA[buf * A_SZ + arow * APAD + aco],
                       A + (size_t)(bm + arow) * 1024 + k0 + aco);
            int wrow = c >> 4, wco = (c & 15) * 8;
            cp_async16(&sW[buf * W_SZ + wrow * WPAD + wco],
                       Wm + (size_t)(k0 + wrow) * 1024 + bn + wco);
        }
    };

#pragma unroll
    for (int s = 0; s < STAGES - 1; s++) {
        stage(s, s * 64);
        CP_COMMIT();
    }

    for (int kt = 0; kt < 16; kt++) {
        CP_WAIT(STAGES - 2);
        __syncthreads();

        int nk = kt + STAGES - 1;
        if (nk < 16) stage(nk % STAGES, nk * 64);
        CP_COMMIT();

        const __half* cA = sA + (kt % STAGES) * A_SZ;
        const __half* cW = sW + (kt % STAGES) * W_SZ;

#pragma unroll
        for (int kk = 0; kk < 64; kk += 16) {
            uint32_t a[4][4], b_[2][4];
#pragma unroll
            for (int mt = 0; mt < 4; mt++)
                ldm_x4(a[mt], &cA[(wm + mt * 16 + lrow) * APAD + kk + lcol]);
#pragma unroll
            for (int np = 0; np < 2; np++)
                ldm_x4_t(b_[np], &cW[(kk + lrow) * WPAD + wn + np * 16 + lcol]);
#pragma unroll
            for (int mt = 0; mt < 4; mt++)
#pragma unroll
                for (int nt = 0; nt < 4; nt++)
                    mma16816(acc[mt][nt], a[mt], &b_[nt >> 1][(nt & 1) * 2]);
        }
    }

    const int g = lane >> 2, t4 = lane & 3;
#pragma unroll
    for (int mt = 0; mt < 4; mt++)
#pragma unroll
        for (int nt = 0; nt < 4; nt++) {
            int m0 = bm + wm + mt * 16 + g;
            int n0 = bn + wn + nt * 8 + t4 * 2;
            float b0 = __ldg(bias + n0), b1 = __ldg(bias + n0 + 1);
            store2(C, O, mode, m0,     n0, acc[mt][nt][0] + b0, acc[mt][nt][1] + b1);
            store2(C, O, mode, m0 + 8, n0, acc[mt][nt][2] + b0, acc[mt][nt][3] + b1);
        }
}

__global__ void __launch_bounds__(256) gemm_qkv_kernel(
    const __half* __restrict__ Aq, const __half* __restrict__ Ak,
    const __half* __restrict__ Av, const __half* __restrict__ Wall,
    const float* __restrict__ bq, const float* __restrict__ bk,
    const float* __restrict__ bv,
    __half* __restrict__ Oq, __half* __restrict__ Ok, __half* __restrict__ Ov)
{
    extern __shared__ __half smem[];
    int z = blockIdx.z;
    const __half* A = (z == 0) ? Aq : (z == 1) ? Ak : Av;
    const float* bias = (z == 0) ? bq : (z == 1) ? bk : bv;
    __half* O = (z == 0) ? Oq : (z == 1) ? Ok : Ov;
    gemm_body(A, Wall + (size_t)z * DD * DD, bias, nullptr, O,
              (z == 0) ? 1 : 2, smem);
}

__global__ void __launch_bounds__(256) gemm_o_kernel(
    const __half* __restrict__ A, const __half* __restrict__ Wm,
    const float* __restrict__ bias, float* __restrict__ C)
{
    extern __shared__ __half smem[];
    gemm_body(A, Wm, bias, C, nullptr, 0, smem);
}

// ---------------------------------------------------------------------------
// Flash attention body — base-2 softmax with ex2.approx.f16x2 (2 exps/MUFU).
// Scores carry SC = 0.125*log2(e); P fp16 pairs come straight from ex2.
// ---------------------------------------------------------------------------
#define KVS 72

__device__ __forceinline__ void attn_body(
    const __half* __restrict__ qg, const __half* __restrict__ kg,
    const __half* __restrict__ vg, __half* __restrict__ out,
    __half* Qs, __half* Kb, __half* Vb, int bh, int r, int qt)
{
    const int tid = threadIdx.x, lane = tid & 31, w = tid >> 5;
    const int q0 = qt * 64;
    const int ntiles = qt + 1;

    const int wq = w * 16;
    const int g = lane >> 2, t4 = lane & 3;
    const int lrow = lane & 15, lcol = (lane >> 4) << 3;
    const int bnrow = ((lane >> 4) << 3) + (lane & 7);
    const int bkoff = ((lane >> 3) & 1) << 3;

    const __half* kbase = kg + (((size_t)bh * 4 + r) * 256) * 64;
    const __half* vbase = vg + (((size_t)bh * 4 + r) * 256) * 64;

#pragma unroll
    for (int j = 0; j < 4; j++) {
        int c = tid + 128 * j, row = c >> 3, co = (c & 7) * 8;
        int i = 4 * (q0 + row) + r;
        *(uint4*)&Qs[row * KVS + co] =
            *(const uint4*)(qg + ((size_t)bh * 1024 + i) * 64 + co);
    }
    __syncthreads();

    auto stage_kv = [&](int buf, int ut) {
#pragma unroll
        for (int j = 0; j < 4; j++) {
            int c = tid + 128 * j, row = c >> 3, co = (c & 7) * 8;
            cp_async16(&Kb[buf * 64 * KVS + row * KVS + co],
                       kbase + (size_t)(ut * 64 + row) * 64 + co);
            cp_async16(&Vb[buf * 64 * KVS + row * KVS + co],
                       vbase + (size_t)(ut * 64 + row) * 64 + co);
        }
    };
    stage_kv(0, 0);
    CP_COMMIT();

    uint32_t qf[4][4];
#pragma unroll
    for (int ks = 0; ks < 4; ks++)
        ldm_x4(qf[ks], &Qs[(wq + lrow) * KVS + ks * 16 + lcol]);

    const int i_g  = 4 * (q0 + wq + g) + r;
    const int i_g8 = i_g + 32;
    float m_g, m_g8, l_g, l_g8;
    float oacc[8][4];
#pragma unroll
    for (int nt = 0; nt < 8; nt++)
#pragma unroll
        for (int c = 0; c < 4; c++) oacc[nt][c] = 0.f;
    {
        float sg[3], sg8[3];
        const int nl_g = min(i_g, 3), nl_g8 = min(i_g8, 3);
#pragma unroll
        for (int l = 0; l < 3; l++) {
            float d0 = 0.f, d1 = 0.f;
            int jg = i_g - 1 - l, jg8 = i_g8 - 1 - l;
            if (l < nl_g) {
                const __half* kp = kg + ((((size_t)bh * 4 + (jg & 3)) * 256 + (jg >> 2)) * 64);
#pragma unroll
                for (int d = 0; d < 16; d += 2) {
                    __half2 a = *(const __half2*)&Qs[(wq + g) * KVS + t4 * 16 + d];
                    __half2 b = *(const __half2*)(kp + t4 * 16 + d);
                    d0 += __half2float(a.x) * __half2float(b.x)
                        + __half2float(a.y) * __half2float(b.y);
                }
            }
            if (l < nl_g8) {
                const __half* kp = kg + ((((size_t)bh * 4 + (jg8 & 3)) * 256 + (jg8 >> 2)) * 64);
#pragma unroll
                for (int d = 0; d < 16; d += 2) {
                    __half2 a = *(const __half2*)&Qs[(wq + g + 8) * KVS + t4 * 16 + d];
                    __half2 b = *(const __half2*)(kp + t4 * 16 + d);
                    d1 += __half2float(a.x) * __half2float(b.x)
                        + __half2float(a.y) * __half2float(b.y);
                }
            }
            d0 += __shfl_xor_sync(0xffffffffu, d0, 1);
            d0 += __shfl_xor_sync(0xffffffffu, d0, 2);
            d1 += __shfl_xor_sync(0xffffffffu, d1, 1);
            d1 += __shfl_xor_sync(0xffffffffu, d1, 2);
            sg[l]  = (l < nl_g)  ? d0 * SC : -1e30f;
            sg8[l] = (l < nl_g8) ? d1 * SC : -1e30f;
        }
        m_g  = fmaxf(fmaxf(sg[0], sg[1]), sg[2]);
        m_g8 = fmaxf(fmaxf(sg8[0], sg8[1]), sg8[2]);
        float p_g[3], p_g8[3];
        l_g = 0.f; l_g8 = 0.f;
#pragma unroll
        for (int l = 0; l < 3; l++) {
            p_g[l]  = (l < nl_g)  ? ex2f(sg[l] - m_g)   : 0.f;
            p_g8[l] = (l < nl_g8) ? ex2f(sg8[l] - m_g8) : 0.f;
            l_g += p_g[l]; l_g8 += p_g8[l];
        }
#pragma unroll
        for (int l = 0; l < 3; l++) {
            int jg = i_g - 1 - l, jg8 = i_g8 - 1 - l;
            if (l < nl_g) {
                const __half* vp = vg + ((((size_t)bh * 4 + (jg & 3)) * 256 + (jg >> 2)) * 64);
#pragma unroll
                for (int nt = 0; nt < 8; nt++) {
                    __half2 v2 = *(const __half2*)(vp + nt * 8 + t4 * 2);
                    oacc[nt][0] += p_g[l] * __half2float(v2.x);
                    oacc[nt][1] += p_g[l] * __half2float(v2.y);
                }
            }
            if (l < nl_g8) {
                const __half* vp = vg + ((((size_t)bh * 4 + (jg8 & 3)) * 256 + (jg8 >> 2)) * 64);
#pragma unroll
                for (int nt = 0; nt < 8; nt++) {
                    __half2 v2 = *(const __half2*)(vp + nt * 8 + t4 * 2);
                    oacc[nt][2] += p_g8[l] * __half2float(v2.x);
                    oacc[nt][3] += p_g8[l] * __half2float(v2.y);
                }
            }
        }
    }

    int buf = 0;
    for (int ut = 0; ut < ntiles; ut++) {
        CP_WAIT(0);
        __syncthreads();
        if (ut + 1 < ntiles) {
            stage_kv(buf ^ 1, ut + 1);
            CP_COMMIT();
        }

        float acc[8][4];
#pragma unroll
        for (int nt = 0; nt < 8; nt++)
#pragma unroll
            for (int c = 0; c < 4; c++) acc[nt][c] = 0.f;
#pragma unroll
        for (int ks = 0; ks < 4; ks++)
#pragma unroll
            for (int nb = 0; nb < 4; nb++) {
                uint32_t bh4[4];
                ldm_x4(bh4, &Kb[buf * 64 * KVS + (nb * 16 + bnrow) * KVS + ks * 16 + bkoff]);
                mma16816(acc[nb * 2 + 0], qf[ks], &bh4[0]);
                mma16816(acc[nb * 2 + 1], qf[ks], &bh4[2]);
            }

        if (ut == qt) {
            const int lim_g = wq + g, lim_g8 = wq + g + 8;
#pragma unroll
            for (int nt = 0; nt < 8; nt++) {
                int u0 = nt * 8 + t4 * 2;
                acc[nt][0] = (u0     <= lim_g)  ? acc[nt][0] * SC : -1e30f;
                acc[nt][1] = (u0 + 1 <= lim_g)  ? acc[nt][1] * SC : -1e30f;
                acc[nt][2] = (u0     <= lim_g8) ? acc[nt][2] * SC : -1e30f;
                acc[nt][3] = (u0 + 1 <= lim_g8) ? acc[nt][3] * SC : -1e30f;
            }
        } else {
#pragma unroll
            for (int nt = 0; nt < 8; nt++)
#pragma unroll
                for (int c = 0; c < 4; c++) acc[nt][c] *= SC;
        }

        float tm_g = -1e30f, tm_g8 = -1e30f;
#pragma unroll
        for (int nt = 0; nt < 8; nt++) {
            tm_g  = fmaxf(tm_g,  fmaxf(acc[nt][0], acc[nt][1]));
            tm_g8 = fmaxf(tm_g8, fmaxf(acc[nt][2], acc[nt][3]));
        }
        tm_g  = fmaxf(tm_g,  __shfl_xor_sync(0xffffffffu, tm_g, 1));
        tm_g  = fmaxf(tm_g,  __shfl_xor_sync(0xffffffffu, tm_g, 2));
        tm_g8 = fmaxf(tm_g8, __shfl_xor_sync(0xffffffffu, tm_g8, 1));
        tm_g8 = fmaxf(tm_g8, __shfl_xor_sync(0xffffffffu, tm_g8, 2));

        float mn_g = fmaxf(m_g, tm_g), mn_g8 = fmaxf(m_g8, tm_g8);
        float al_g = ex2f(m_g - mn_g), al_g8 = ex2f(m_g8 - mn_g8);
        m_g = mn_g; m_g8 = mn_g8;

        // P = 2^(s - m) as packed fp16 pairs, straight into mma A-fragment words
        uint32_t pb[8][2];
        float ps_g = 0.f, ps_g8 = 0.f;
#pragma unroll
        for (int nt = 0; nt < 8; nt++) {
            pb[nt][0] = ex2_h2(acc[nt][0] - mn_g,  acc[nt][1] - mn_g);
            pb[nt][1] = ex2_h2(acc[nt][2] - mn_g8, acc[nt][3] - mn_g8);
            ps_g  += sum_h2(pb[nt][0]);
            ps_g8 += sum_h2(pb[nt][1]);
        }
        ps_g  += __shfl_xor_sync(0xffffffffu, ps_g, 1);
        ps_g  += __shfl_xor_sync(0xffffffffu, ps_g, 2);
        ps_g8 += __shfl_xor_sync(0xffffffffu, ps_g8, 1);
        ps_g8 += __shfl_xor_sync(0xffffffffu, ps_g8, 2);
        l_g = l_g * al_g + ps_g;
        l_g8 = l_g8 * al_g8 + ps_g8;
#pragma unroll
        for (int nt = 0; nt < 8; nt++) {
            oacc[nt][0] *= al_g;  oacc[nt][1] *= al_g;
            oacc[nt][2] *= al_g8; oacc[nt][3] *= al_g8;
        }

#pragma unroll
        for (int ks = 0; ks < 4; ks++) {
            uint32_t pa[4];
            pa[0] = pb[2 * ks][0];
            pa[1] = pb[2 * ks][1];
            pa[2] = pb[2 * ks + 1][0];
            pa[3] = pb[2 * ks + 1][1];
#pragma unroll
            for (int nb = 0; nb < 4; nb++) {
                uint32_t vh4[4];
                ldm_x4_t(vh4, &Vb[buf * 64 * KVS + (ks * 16 + lrow) * KVS + nb * 16 + lcol]);
                mma16816(oacc[nb * 2 + 0], pa, &vh4[0]);
                mma16816(oacc[nb * 2 + 1], pa, &vh4[2]);
            }
        }
        buf ^= 1;
    }

    __syncthreads();
    {
        float inv_g = 1.0f / l_g, inv_g8 = 1.0f / l_g8;
#pragma unroll
        for (int nt = 0; nt < 8; nt++) {
            *(__half2*)&Qs[(wq + g) * KVS + nt * 8 + t4 * 2] =
                __floats2half2_rn(oacc[nt][0] * inv_g, oacc[nt][1] * inv_g);
            *(__half2*)&Qs[(wq + g + 8) * KVS + nt * 8 + t4 * 2] =
                __floats2half2_rn(oacc[nt][2] * inv_g8, oacc[nt][3] * inv_g8);
        }
    }
    __syncthreads();
    {
        int bb = bh >> 4, h = bh & 15;
#pragma unroll
        for (int j = 0; j < 4; j++) {
            int c = tid + 128 * j, row = c >> 3, co = (c & 7) * 8;
            int i = 4 * (q0 + row) + r;
            *(uint4*)(out + ((size_t)(bb * 1024 + i)) * 1024 + h * 64 + co) =
                *(const uint4*)&Qs[row * KVS + co];
        }
    }
    __syncthreads();
}

__global__ void __launch_bounds__(128) attn_flash_kernel(
    const __half* __restrict__ qg, const __half* __restrict__ kg,
    const __half* __restrict__ vg, __half* __restrict__ out)
{
    __shared__ __half Qs[64 * KVS];
    __shared__ __half Kb[2 * 64 * KVS];
    __shared__ __half Vb[2 * 64 * KVS];

    const int p  = blockIdx.x >> 8;
    const int bh = (blockIdx.x & 255) >> 2;
    const int r  = blockIdx.x & 3;
    const int qtA = (p == 0) ? 3 : 2;
    const int qtB = (p == 0) ? 0 : 1;

    attn_body(qg, kg, vg, out, Qs, Kb, Vb, bh, r, qtA);
    attn_body(qg, kg, vg, out, Qs, Kb, Vb, bh, r, qtB);
}

// ---------------------------------------------------------------------------
extern "C" void kernel_launch(void* const* d_in, const int* in_sizes, int n_in,
                              void* d_out, int out_size)
{
    const float* Q  = (const float*)d_in[0];
    const float* K  = (const float*)d_in[1];
    const float* V  = (const float*)d_in[2];
    const float* Wq = (const float*)d_in[3];
    const float* bq = (const float*)d_in[4];
    const float* Wk = (const float*)d_in[5];
    const float* bk = (const float*)d_in[6];
    const float* Wv = (const float*)d_in[7];
    const float* bv = (const float*)d_in[8];
    const float* Wo = (const float*)d_in[9];
    const float* bo = (const float*)d_in[10];
    float* out = (float*)d_out;

    __half *pqin, *pkin, *pvin, *pw, *pq, *pk, *pv, *pah;
    cudaGetSymbolAddress((void**)&pqin, g_qin);
    cudaGetSymbolAddress((void**)&pkin, g_kin);
    cudaGetSymbolAddress((void**)&pvin, g_vin);
    cudaGetSymbolAddress((void**)&pw, g_w);
    cudaGetSymbolAddress((void**)&pq, g_q);
    cudaGetSymbolAddress((void**)&pk, g_k);
    cudaGetSymbolAddress((void**)&pv, g_v);
    cudaGetSymbolAddress((void**)&pah, g_attn);

    cudaFuncSetAttribute(gemm_qkv_kernel,
                         cudaFuncAttributeMaxDynamicSharedMemorySize, GEMM_SMEM);
    cudaFuncSetAttribute(gemm_o_kernel,
                         cudaFuncAttributeMaxDynamicSharedMemorySize, GEMM_SMEM);

    convall_kernel<<<4096, 256>>>(Q, K, V, Wq, Wk, Wv, Wo, pqin, pkin, pvin, pw);

    gemm_qkv_kernel<<<dim3(8, 32, 3), 256, GEMM_SMEM>>>(
        pqin, pkin, pvin, pw, bq, bk, bv, pq, pk, pv);

    attn_flash_kernel<<<512, 128>>>(pq, pk, pv, pah);

    gemm_o_kernel<<<dim3(8, 32), 256, GEMM_SMEM>>>(
        pah, pw + 3 * (size_t)DD * DD, bo, out);
}

// round 16
// speedup vs baseline: 1.3352x; 1.0051x over previous
#include <cuda_runtime.h>
#include <cuda_fp16.h>
#include <cstdint>

#define BB 4
#define SS 1024
#define DD 1024
#define HH 16
#define DK 64
#define NEL (BB * HH * SS * DK)   // 4M

__device__ __half g_qin[NEL], g_kin[NEL], g_vin[NEL];
__device__ __half g_w[4 * DD * DD];
__device__ __half g_q[NEL];          // [bh][s][d]
__device__ __half g_k[NEL];          // [bh][r][u][d]
__device__ __half g_v[NEL];          // [bh][r][u][d]
__device__ __half g_attn[BB * SS * DD];

#define SC 0.18033688011112042f     // 0.125 * log2(e)

// ---------------------------------------------------------------------------
__device__ __forceinline__ unsigned saddr(const void* p) {
    return (unsigned)__cvta_generic_to_shared(p);
}
__device__ __forceinline__ void ldm_x4(uint32_t* r, const void* p) {
    asm volatile("ldmatrix.sync.aligned.m8n8.x4.shared.b16 {%0,%1,%2,%3}, [%4];"
        : "=r"(r[0]), "=r"(r[1]), "=r"(r[2]), "=r"(r[3]) : "r"(saddr(p)));
}
__device__ __forceinline__ void ldm_x4_t(uint32_t* r, const void* p) {
    asm volatile("ldmatrix.sync.aligned.m8n8.x4.trans.shared.b16 {%0,%1,%2,%3}, [%4];"
        : "=r"(r[0]), "=r"(r[1]), "=r"(r[2]), "=r"(r[3]) : "r"(saddr(p)));
}
__device__ __forceinline__ void mma16816(float* c, const uint32_t* a, const uint32_t* b) {
    asm volatile("mma.sync.aligned.m16n8k16.row.col.f32.f16.f16.f32 "
        "{%0,%1,%2,%3},{%4,%5,%6,%7},{%8,%9},{%0,%1,%2,%3};"
        : "+f"(c[0]), "+f"(c[1]), "+f"(c[2]), "+f"(c[3])
        : "r"(a[0]), "r"(a[1]), "r"(a[2]), "r"(a[3]), "r"(b[0]), "r"(b[1]));
}
__device__ __forceinline__ void cp_async16(void* s, const void* g) {
    asm volatile("cp.async.cg.shared.global [%0], [%1], 16;"
        :: "r"(saddr(s)), "l"(g));
}
#define CP_COMMIT() asm volatile("cp.async.commit_group;" ::: "memory")
#define CP_WAIT(n)  asm volatile("cp.async.wait_group %0;" :: "n"(n) : "memory")

__device__ __forceinline__ uint32_t packh2(float a, float b) {
    __half2 p = __floats2half2_rn(a, b);
    return *(uint32_t*)&p;
}
__device__ __forceinline__ float ex2f(float x) {
    float y;
    asm("ex2.approx.f32 %0, %1;" : "=f"(y) : "f"(x));
    return y;
}
__device__ __forceinline__ uint32_t ex2_h2(float a, float b) {
    __half2 h = __floats2half2_rn(a, b);
    uint32_t u = *(uint32_t*)&h, r;
    asm("ex2.approx.f16x2 %0, %1;" : "=r"(r) : "r"(u));
    return r;
}
__device__ __forceinline__ float sum_h2(uint32_t u) {
    __half2 h = *(__half2*)&u;
    return __half2float(h.x) + __half2float(h.y);
}

// ---------------------------------------------------------------------------
// Fused prep: fp32->fp16, 2048 blocks, 8 float4 per thread (MLP=8).
// ---------------------------------------------------------------------------
__global__ void __launch_bounds__(256) convall_kernel(
    const float* __restrict__ Q, const float* __restrict__ K,
    const float* __restrict__ V,
    const float* __restrict__ W0, const float* __restrict__ W1,
    const float* __restrict__ W2, const float* __restrict__ W3,
    __half* __restrict__ dq, __half* __restrict__ dk, __half* __restrict__ dv,
    __half* __restrict__ dw)
{
    int b = blockIdx.x;
    const float* src;
    __half* dst;
    int lb;
    if (b < 512)        { src = Q; dst = dq; lb = b; }
    else if (b < 1024)  { src = K; dst = dk; lb = b - 512; }
    else if (b < 1536)  { src = V; dst = dv; lb = b - 1024; }
    else {
        int wb = b - 1536;
        int wz = wb >> 7;
        src = (wz == 0) ? W0 : (wz == 1) ? W1 : (wz == 2) ? W2 : W3;
        dst = dw + (size_t)wz * DD * DD;
        lb = wb & 127;
    }
    float4 v[8];
    size_t base = (size_t)lb * 2048 + threadIdx.x;   // float4 units
#pragma unroll
    for (int it = 0; it < 8; it++)
        v[it] = *(const float4*)(src + (base + it * 256) * 4);
#pragma unroll
    for (int it = 0; it < 8; it++) {
        uint2 u; u.x = packh2(v[it].x, v[it].y); u.y = packh2(v[it].z, v[it].w);
        *(uint2*)(dst + (base + it * 256) * 4) = u;
    }
}

// ---------------------------------------------------------------------------
// fp16 GEMM (R14 frozen): BK=64, 3-stage cp.async, 256 thr, 64x32 warp tiles.
// ---------------------------------------------------------------------------
#define APAD 72
#define WPAD 136
#define A_SZ (128 * APAD)
#define W_SZ (64 * WPAD)
#define STAGES 3
#define GEMM_SMEM (STAGES * (A_SZ + W_SZ) * 2)   // 107,520 bytes

__device__ __forceinline__ void store2(
    float* __restrict__ C, __half* __restrict__ O, int mode,
    int m, int n, float v0, float v1)
{
    if (mode == 0) {
        *(float2*)(C + (size_t)m * 1024 + n) = make_float2(v0, v1);
        return;
    }
    int b = m >> 10, s = m & 1023, h = n >> 6, d = n & 63;
    size_t idx;
    if (mode == 1) idx = (((size_t)(b * 16 + h)) * 1024 + s) * 64 + d;
    else           idx = ((((size_t)(b * 16 + h)) * 4 + (s & 3)) * 256 + (s >> 2)) * 64 + d;
    __half2 p = __floats2half2_rn(v0, v1);
    *(__half2*)(O + idx) = p;
}

__device__ __forceinline__ void gemm_body(
    const __half* __restrict__ A, const __half* __restrict__ Wm,
    const float* __restrict__ bias, float* __restrict__ C,
    __half* __restrict__ O, int mode, __half* smem)
{
    __half* sA = smem;
    __half* sW = smem + STAGES * A_SZ;

    const int tid = threadIdx.x;
    const int bm = blockIdx.y * 128, bn = blockIdx.x * 128;
    const int w = tid >> 5, lane = tid & 31;
    const int wm = (w & 1) * 64, wn = (w >> 1) * 32;
    const int lrow = lane & 15, lcol = (lane >> 4) << 3;

    float acc[4][4][4];
#pragma unroll
    for (int i = 0; i < 4; i++)
#pragma unroll
        for (int j = 0; j < 4; j++)
#pragma unroll
            for (int t = 0; t < 4; t++) acc[i][j][t] = 0.f;

    auto stage = [&](int buf, int k0) {
#pragma unroll
        for (int j = 0; j < 4; j++) {
            int c = tid + 256 * j;
            int arow = c >> 3, aco = (c & 7) * 8;
            cp_async16(&sA[buf * A_SZ + arow * APAD + aco],
                       A + (size_t)(bm + arow) * 1024 + k0 + aco);
            int wrow = c >> 4, wco = (c & 15) * 8;
            cp_async16(&sW[buf * W_SZ + wrow * WPAD + wco],
                       Wm + (size_t)(k0 + wrow) * 1024 + bn + wco);
        }
    };

#pragma unroll
    for (int s = 0; s < STAGES - 1; s++) {
        stage(s, s * 64);
        CP_COMMIT();
    }

    for (int kt = 0; kt < 16; kt++) {
        CP_WAIT(STAGES - 2);
        __syncthreads();

        int nk = kt + STAGES - 1;
        if (nk < 16) stage(nk % STAGES, nk * 64);
        CP_COMMIT();

        const __half* cA = sA + (kt % STAGES) * A_SZ;
        const __half* cW = sW + (kt % STAGES) * W_SZ;

#pragma unroll
        for (int kk = 0; kk < 64; kk += 16) {
            uint32_t a[4][4], b_[2][4];
#pragma unroll
            for (int mt = 0; mt < 4; mt++)
                ldm_x4(a[mt], &cA[(wm + mt * 16 + lrow) * APAD + kk + lcol]);
#pragma unroll
            for (int np = 0; np < 2; np++)
                ldm_x4_t(b_[np], &cW[(kk + lrow) * WPAD + wn + np * 16 + lcol]);
#pragma unroll
            for (int mt = 0; mt < 4; mt++)
#pragma unroll
                for (int nt = 0; nt < 4; nt++)
                    mma16816(acc[mt][nt], a[mt], &b_[nt >> 1][(nt & 1) * 2]);
        }
    }

    const int g = lane >> 2, t4 = lane & 3;
#pragma unroll
    for (int mt = 0; mt < 4; mt++)
#pragma unroll
        for (int nt = 0; nt < 4; nt++) {
            int m0 = bm + wm + mt * 16 + g;
            int n0 = bn + wn + nt * 8 + t4 * 2;
            float b0 = __ldg(bias + n0), b1 = __ldg(bias + n0 + 1);
            store2(C, O, mode, m0,     n0, acc[mt][nt][0] + b0, acc[mt][nt][1] + b1);
            store2(C, O, mode, m0 + 8, n0, acc[mt][nt][2] + b0, acc[mt][nt][3] + b1);
        }
}

__global__ void __launch_bounds__(256) gemm_qkv_kernel(
    const __half* __restrict__ Aq, const __half* __restrict__ Ak,
    const __half* __restrict__ Av, const __half* __restrict__ Wall,
    const float* __restrict__ bq, const float* __restrict__ bk,
    const float* __restrict__ bv,
    __half* __restrict__ Oq, __half* __restrict__ Ok, __half* __restrict__ Ov)
{
    extern __shared__ __half smem[];
    int z = blockIdx.z;
    const __half* A = (z == 0) ? Aq : (z == 1) ? Ak : Av;
    const float* bias = (z == 0) ? bq : (z == 1) ? bk : bv;
    __half* O = (z == 0) ? Oq : (z == 1) ? Ok : Ov;
    gemm_body(A, Wall + (size_t)z * DD * DD, bias, nullptr, O,
              (z == 0) ? 1 : 2, smem);
}

__global__ void __launch_bounds__(256) gemm_o_kernel(
    const __half* __restrict__ A, const __half* __restrict__ Wm,
    const float* __restrict__ bias, float* __restrict__ C)
{
    extern __shared__ __half smem[];
    gemm_body(A, Wm, bias, C, nullptr, 0, smem);
}

// ---------------------------------------------------------------------------
// Fused warp-group flash attention: 256 threads = 2 warp-groups processing
// two q-tiles of the SAME (bh, r) over ONE shared K/V tile stream.
// Flavor 0 pairs qt (3, 0); flavor 1 pairs (2, 1). Heavy flavor first.
// Dynamic smem: Qs[2][64*KVS] | Kb[2][64*KVS] | Vb[2][64*KVS] = 55,296 B.
// ---------------------------------------------------------------------------
#define KVS 72
#define TB (64 * KVS)                 // halfs per tile region (4608)
#define ATTN_SMEM (6 * TB * 2)        // 55,296 bytes

__global__ void __launch_bounds__(256, 2) attn2_kernel(
    const __half* __restrict__ qg, const __half* __restrict__ kg,
    const __half* __restrict__ vg, __half* __restrict__ out)
{
    extern __shared__ __half sm2[];
    __half* Qs = sm2;             // [2][TB]  (per warp-group)
    __half* Kb = sm2 + 2 * TB;    // [2][TB]  (double buffer)
    __half* Vb = sm2 + 4 * TB;    // [2][TB]

    const int tid = threadIdx.x, lane = tid & 31;
    const int wg = tid >> 7;             // warp-group 0/1
    const int wt = tid & 127;            // wg-local tid
    const int w4 = (tid >> 5) & 3;       // warp within wg
    const int flavor = blockIdx.x >> 8;  // 0: (3,0)  1: (2,1)
    const int bh = (blockIdx.x & 255) >> 2;
    const int r  = blockIdx.x & 3;
    const int qt = (flavor == 0) ? (wg ? 0 : 3) : (wg ? 1 : 2);
    const int ntb = (flavor == 0) ? 4 : 3;
    const int q0 = qt * 64;

    __half* Qw = Qs + wg * TB;

    const int wq = w4 * 16;
    const int g = lane >> 2, t4 = lane & 3;
    const int lrow = lane & 15, lcol = (lane >> 4) << 3;
    const int bnrow = ((lane >> 4) << 3) + (lane & 7);
    const int bkoff = ((lane >> 3) & 1) << 3;

    const __half* kbase = kg + (((size_t)bh * 4 + r) * 256) * 64;
    const __half* vbase = vg + (((size_t)bh * 4 + r) * 256) * 64;

    // load Q (per wg: 128 threads x 4 iters over 512 16B-chunks)
#pragma unroll
    for (int j = 0; j < 4; j++) {
        int c = wt + 128 * j, row = c >> 3, co = (c & 7) * 8;
        int i = 4 * (q0 + row) + r;
        *(uint4*)&Qw[row * KVS + co] =
            *(const uint4*)(qg + ((size_t)bh * 1024 + i) * 64 + co);
    }
    __syncthreads();

    // stage K/V tile ut into buffer buf (all 256 threads)
    auto stage_kv = [&](int buf, int ut) {
#pragma unroll
        for (int j = 0; j < 2; j++) {
            int c = tid + 256 * j, row = c >> 3, co = (c & 7) * 8;
            cp_async16(&Kb[buf * TB + row * KVS + co],
                       kbase + (size_t)(ut * 64 + row) * 64 + co);
            cp_async16(&Vb[buf * TB + row * KVS + co],
                       vbase + (size_t)(ut * 64 + row) * 64 + co);
        }
    };
    stage_kv(0, 0);
    CP_COMMIT();

    uint32_t qf[4][4];
#pragma unroll
    for (int ks = 0; ks < 4; ks++)
        ldm_x4(qf[ks], &Qw[(wq + lrow) * KVS + ks * 16 + lcol]);

    const int i_g  = 4 * (q0 + wq + g) + r;
    const int i_g8 = i_g + 32;
    float m_g, m_g8, l_g, l_g8;
    float oacc[8][4];
#pragma unroll
    for (int nt = 0; nt < 8; nt++)
#pragma unroll
        for (int c = 0; c < 4; c++) oacc[nt][c] = 0.f;

    // locals pre-tile (j = i-1..i-3), per warp-group
    {
        float sg[3], sg8[3];
        const int nl_g = min(i_g, 3), nl_g8 = min(i_g8, 3);
#pragma unroll
        for (int l = 0; l < 3; l++) {
            float d0 = 0.f, d1 = 0.f;
            int jg = i_g - 1 - l, jg8 = i_g8 - 1 - l;
            if (l < nl_g) {
                const __half* kp = kg + ((((size_t)bh * 4 + (jg & 3)) * 256 + (jg >> 2)) * 64);
#pragma unroll
                for (int d = 0; d < 16; d += 2) {
                    __half2 a = *(const __half2*)&Qw[(wq + g) * KVS + t4 * 16 + d];
                    __half2 b = *(const __half2*)(kp + t4 * 16 + d);
                    d0 += __half2float(a.x) * __half2float(b.x)
                        + __half2float(a.y) * __half2float(b.y);
                }
            }
            if (l < nl_g8) {
                const __half* kp = kg + ((((size_t)bh * 4 + (jg8 & 3)) * 256 + (jg8 >> 2)) * 64);
#pragma unroll
                for (int d = 0; d < 16; d += 2) {
                    __half2 a = *(const __half2*)&Qw[(wq + g + 8) * KVS + t4 * 16 + d];
                    __half2 b = *(const __half2*)(kp + t4 * 16 + d);
                    d1 += __half2float(a.x) * __half2float(b.x)
                        + __half2float(a.y) * __half2float(b.y);
                }
            }
            d0 += __shfl_xor_sync(0xffffffffu, d0, 1);
            d0 += __shfl_xor_sync(0xffffffffu, d0, 2);
            d1 += __shfl_xor_sync(0xffffffffu, d1, 1);
            d1 += __shfl_xor_sync(0xffffffffu, d1, 2);
            sg[l]  = (l < nl_g)  ? d0 * SC : -1e30f;
            sg8[l] = (l < nl_g8) ? d1 * SC : -1e30f;
        }
        m_g  = fmaxf(fmaxf(sg[0], sg[1]), sg[2]);
        m_g8 = fmaxf(fmaxf(sg8[0], sg8[1]), sg8[2]);
        float p_g[3], p_g8[3];
        l_g = 0.f; l_g8 = 0.f;
#pragma unroll
        for (int l = 0; l < 3; l++) {
            p_g[l]  = (l < nl_g)  ? ex2f(sg[l] - m_g)   : 0.f;
            p_g8[l] = (l < nl_g8) ? ex2f(sg8[l] - m_g8) : 0.f;
            l_g += p_g[l]; l_g8 += p_g8[l];
        }
#pragma unroll
        for (int l = 0; l < 3; l++) {
            int jg = i_g - 1 - l, jg8 = i_g8 - 1 - l;
            if (l < nl_g) {
                const __half* vp = vg + ((((size_t)bh * 4 + (jg & 3)) * 256 + (jg >> 2)) * 64);
#pragma unroll
                for (int nt = 0; nt < 8; nt++) {
                    __half2 v2 = *(const __half2*)(vp + nt * 8 + t4 * 2);
                    oacc[nt][0] += p_g[l] * __half2float(v2.x);
                    oacc[nt][1] += p_g[l] * __half2float(v2.y);
                }
            }
            if (l < nl_g8) {
                const __half* vp = vg + ((((size_t)bh * 4 + (jg8 & 3)) * 256 + (jg8 >> 2)) * 64);
#pragma unroll
                for (int nt = 0; nt < 8; nt++) {
                    __half2 v2 = *(const __half2*)(vp + nt * 8 + t4 * 2);
                    oacc[nt][2] += p_g8[l] * __half2float(v2.x);
                    oacc[nt][3] += p_g8[l] * __half2float(v2.y);
                }
            }
        }
    }

    int buf = 0;
    for (int ut = 0; ut < ntb; ut++) {
        CP_WAIT(0);
        __syncthreads();
        if (ut + 1 < ntb) {
            stage_kv(buf ^ 1, ut + 1);
            CP_COMMIT();
        }

        if (ut <= qt) {
            float acc[8][4];
#pragma unroll
            for (int nt = 0; nt < 8; nt++)
#pragma unroll
                for (int c = 0; c < 4; c++) acc[nt][c] = 0.f;
#pragma unroll
            for (int ks = 0; ks < 4; ks++)
#pragma unroll
                for (int nb = 0; nb < 4; nb++) {
                    uint32_t bh4[4];
                    ldm_x4(bh4, &Kb[buf * TB + (nb * 16 + bnrow) * KVS + ks * 16 + bkoff]);
                    mma16816(acc[nb * 2 + 0], qf[ks], &bh4[0]);
                    mma16816(acc[nb * 2 + 1], qf[ks], &bh4[2]);
                }

            if (ut == qt) {
                const int lim_g = wq + g, lim_g8 = wq + g + 8;
#pragma unroll
                for (int nt = 0; nt < 8; nt++) {
                    int u0 = nt * 8 + t4 * 2;
                    acc[nt][0] = (u0     <= lim_g)  ? acc[nt][0] * SC : -1e30f;
                    acc[nt][1] = (u0 + 1 <= lim_g)  ? acc[nt][1] * SC : -1e30f;
                    acc[nt][2] = (u0     <= lim_g8) ? acc[nt][2] * SC : -1e30f;
                    acc[nt][3] = (u0 + 1 <= lim_g8) ? acc[nt][3] * SC : -1e30f;
                }
            } else {
#pragma unroll
                for (int nt = 0; nt < 8; nt++)
#pragma unroll
                    for (int c = 0; c < 4; c++) acc[nt][c] *= SC;
            }

            float tm_g = -1e30f, tm_g8 = -1e30f;
#pragma unroll
            for (int nt = 0; nt < 8; nt++) {
                tm_g  = fmaxf(tm_g,  fmaxf(acc[nt][0], acc[nt][1]));
                tm_g8 = fmaxf(tm_g8, fmaxf(acc[nt][2], acc[nt][3]));
            }
            tm_g  = fmaxf(tm_g,  __shfl_xor_sync(0xffffffffu, tm_g, 1));
            tm_g  = fmaxf(tm_g,  __shfl_xor_sync(0xffffffffu, tm_g, 2));
            tm_g8 = fmaxf(tm_g8, __shfl_xor_sync(0xffffffffu, tm_g8, 1));
            tm_g8 = fmaxf(tm_g8, __shfl_xor_sync(0xffffffffu, tm_g8, 2));

            float mn_g = fmaxf(m_g, tm_g), mn_g8 = fmaxf(m_g8, tm_g8);
            float al_g = ex2f(m_g - mn_g), al_g8 = ex2f(m_g8 - mn_g8);
            m_g = mn_g; m_g8 = mn_g8;

            uint32_t pb[8][2];
            float ps_g = 0.f, ps_g8 = 0.f;
#pragma unroll
            for (int nt = 0; nt < 8; nt++) {
                pb[nt][0] = ex2_h2(acc[nt][0] - mn_g,  acc[nt][1] - mn_g);
                pb[nt][1] = ex2_h2(acc[nt][2] - mn_g8, acc[nt][3] - mn_g8);
                ps_g  += sum_h2(pb[nt][0]);
                ps_g8 += sum_h2(pb[nt][1]);
            }
            ps_g  += __shfl_xor_sync(0xffffffffu, ps_g, 1);
            ps_g  += __shfl_xor_sync(0xffffffffu, ps_g, 2);
            ps_g8 += __shfl_xor_sync(0xffffffffu, ps_g8, 1);
            ps_g8 += __shfl_xor_sync(0xffffffffu, ps_g8, 2);
            l_g = l_g * al_g + ps_g;
            l_g8 = l_g8 * al_g8 + ps_g8;
#pragma unroll
            for (int nt = 0; nt < 8; nt++) {
                oacc[nt][0] *= al_g;  oacc[nt][1] *= al_g;
                oacc[nt][2] *= al_g8; oacc[nt][3] *= al_g8;
            }

#pragma unroll
            for (int ks = 0; ks < 4; ks++) {
                uint32_t pa[4];
                pa[0] = pb[2 * ks][0];
                pa[1] = pb[2 * ks][1];
                pa[2] = pb[2 * ks + 1][0];
                pa[3] = pb[2 * ks + 1][1];
#pragma unroll
                for (int nb = 0; nb < 4; nb++) {
                    uint32_t vh4[4];
                    ldm_x4_t(vh4, &Vb[buf * TB + (ks * 16 + lrow) * KVS + nb * 16 + lcol]);
                    mma16816(oacc[nb * 2 + 0], pa, &vh4[0]);
                    mma16816(oacc[nb * 2 + 1], pa, &vh4[2]);
                }
            }
        }
        buf ^= 1;
    }

    // normalize into Qw (warp-private rows, no pre-sync needed)
    {
        float inv_g = 1.0f / l_g, inv_g8 = 1.0f / l_g8;
#pragma unroll
        for (int nt = 0; nt < 8; nt++) {
            *(__half2*)&Qw[(wq + g) * KVS + nt * 8 + t4 * 2] =
                __floats2half2_rn(oacc[nt][0] * inv_g, oacc[nt][1] * inv_g);
            *(__half2*)&Qw[(wq + g + 8) * KVS + nt * 8 + t4 * 2] =
                __floats2half2_rn(oacc[nt][2] * inv_g8, oacc[nt][3] * inv_g8);
        }
    }
    __syncthreads();
    {
        int bb = bh >> 4, h = bh & 15;
#pragma unroll
        for (int j = 0; j < 4; j++) {
            int c = wt + 128 * j, row = c >> 3, co = (c & 7) * 8;
            int i = 4 * (q0 + row) + r;
            *(uint4*)(out + ((size_t)(bb * 1024 + i)) * 1024 + h * 64 + co) =
                *(const uint4*)&Qw[row * KVS + co];
        }
    }
}

// ---------------------------------------------------------------------------
extern "C" void kernel_launch(void* const* d_in, const int* in_sizes, int n_in,
                              void* d_out, int out_size)
{
    const float* Q  = (const float*)d_in[0];
    const float* K  = (const float*)d_in[1];
    const float* V  = (const float*)d_in[2];
    const float* Wq = (const float*)d_in[3];
    const float* bq = (const float*)d_in[4];
    const float* Wk = (const float*)d_in[5];
    const float* bk = (const float*)d_in[6];
    const float* Wv = (const float*)d_in[7];
    const float* bv = (const float*)d_in[8];
    const float* Wo = (const float*)d_in[9];
    const float* bo = (const float*)d_in[10];
    float* out = (float*)d_out;

    __half *pqin, *pkin, *pvin, *pw, *pq, *pk, *pv, *pah;
    cudaGetSymbolAddress((void**)&pqin, g_qin);
    cudaGetSymbolAddress((void**)&pkin, g_kin);
    cudaGetSymbolAddress((void**)&pvin, g_vin);
    cudaGetSymbolAddress((void**)&pw, g_w);
    cudaGetSymbolAddress((void**)&pq, g_q);
    cudaGetSymbolAddress((void**)&pk, g_k);
    cudaGetSymbolAddress((void**)&pv, g_v);
    cudaGetSymbolAddress((void**)&pah, g_attn);

    cudaFuncSetAttribute(gemm_qkv_kernel,
                         cudaFuncAttributeMaxDynamicSharedMemorySize, GEMM_SMEM);
    cudaFuncSetAttribute(gemm_o_kernel,
                         cudaFuncAttributeMaxDynamicSharedMemorySize, GEMM_SMEM);
    cudaFuncSetAttribute(attn2_kernel,
                         cudaFuncAttributeMaxDynamicSharedMemorySize, ATTN_SMEM);

    convall_kernel<<<2048, 256>>>(Q, K, V, Wq, Wk, Wv, Wo, pqin, pkin, pvin, pw);

    gemm_qkv_kernel<<<dim3(8, 32, 3), 256, GEMM_SMEM>>>(
        pqin, pkin, pvin, pw, bq, bk, bv, pq, pk, pv);

    attn2_kernel<<<512, 256, ATTN_SMEM>>>(pq, pk, pv, pah);

    gemm_o_kernel<<<dim3(8, 32), 256, GEMM_SMEM>>>(
        pah, pw + 3 * (size_t)DD * DD, bo, out);
}

// round 17
// speedup vs baseline: 1.4274x; 1.0691x over previous
#include <cuda_runtime.h>
#include <cuda_fp16.h>
#include <cstdint>

#define BB 4
#define SS 1024
#define DD 1024
#define HH 16
#define DK 64
#define NEL (BB * HH * SS * DK)   // 4M

__device__ __half g_qin[NEL], g_kin[NEL], g_vin[NEL];
__device__ __half g_w[4 * DD * DD];
__device__ __half g_q[NEL];          // [bh][s][d]
__device__ __half g_k[NEL];          // [bh][r][u][d]
__device__ __half g_v[NEL];          // [bh][r][u][d]
__device__ __half g_attn[BB * SS * DD];

#define SC 0.18033688011112042f     // 0.125 * log2(e)

// ---------------------------------------------------------------------------
__device__ __forceinline__ unsigned saddr(const void* p) {
    return (unsigned)__cvta_generic_to_shared(p);
}
__device__ __forceinline__ void ldm_x4(uint32_t* r, const void* p) {
    asm volatile("ldmatrix.sync.aligned.m8n8.x4.shared.b16 {%0,%1,%2,%3}, [%4];"
        : "=r"(r[0]), "=r"(r[1]), "=r"(r[2]), "=r"(r[3]) : "r"(saddr(p)));
}
__device__ __forceinline__ void ldm_x4_t(uint32_t* r, const void* p) {
    asm volatile("ldmatrix.sync.aligned.m8n8.x4.trans.shared.b16 {%0,%1,%2,%3}, [%4];"
        : "=r"(r[0]), "=r"(r[1]), "=r"(r[2]), "=r"(r[3]) : "r"(saddr(p)));
}
__device__ __forceinline__ void mma16816(float* c, const uint32_t* a, const uint32_t* b) {
    asm volatile("mma.sync.aligned.m16n8k16.row.col.f32.f16.f16.f32 "
        "{%0,%1,%2,%3},{%4,%5,%6,%7},{%8,%9},{%0,%1,%2,%3};"
        : "+f"(c[0]), "+f"(c[1]), "+f"(c[2]), "+f"(c[3])
        : "r"(a[0]), "r"(a[1]), "r"(a[2]), "r"(a[3]), "r"(b[0]), "r"(b[1]));
}
__device__ __forceinline__ void cp_async16(void* s, const void* g) {
    asm volatile("cp.async.cg.shared.global [%0], [%1], 16;"
        :: "r"(saddr(s)), "l"(g));
}
#define CP_COMMIT() asm volatile("cp.async.commit_group;" ::: "memory")
#define CP_WAIT(n)  asm volatile("cp.async.wait_group %0;" :: "n"(n) : "memory")

__device__ __forceinline__ uint32_t packh2(float a, float b) {
    __half2 p = __floats2half2_rn(a, b);
    return *(uint32_t*)&p;
}
__device__ __forceinline__ float ex2f(float x) {
    float y;
    asm("ex2.approx.f32 %0, %1;" : "=f"(y) : "f"(x));
    return y;
}
__device__ __forceinline__ uint32_t ex2_h2(float a, float b) {
    __half2 h = __floats2half2_rn(a, b);
    uint32_t u = *(uint32_t*)&h, r;
    asm("ex2.approx.f16x2 %0, %1;" : "=r"(r) : "r"(u));
    return r;
}
__device__ __forceinline__ float sum_h2(uint32_t u) {
    __half2 h = *(__half2*)&u;
    return __half2float(h.x) + __half2float(h.y);
}

// ---------------------------------------------------------------------------
// Fused prep: fp32->fp16, 2048 blocks, 8 float4 per thread (MLP=8).
// ---------------------------------------------------------------------------
__global__ void __launch_bounds__(256) convall_kernel(
    const float* __restrict__ Q, const float* __restrict__ K,
    const float* __restrict__ V,
    const float* __restrict__ W0, const float* __restrict__ W1,
    const float* __restrict__ W2, const float* __restrict__ W3,
    __half* __restrict__ dq, __half* __restrict__ dk, __half* __restrict__ dv,
    __half* __restrict__ dw)
{
    int b = blockIdx.x;
    const float* src;
    __half* dst;
    int lb;
    if (b < 512)        { src = Q; dst = dq; lb = b; }
    else if (b < 1024)  { src = K; dst = dk; lb = b - 512; }
    else if (b < 1536)  { src = V; dst = dv; lb = b - 1024; }
    else {
        int wb = b - 1536;
        int wz = wb >> 7;
        src = (wz == 0) ? W0 : (wz == 1) ? W1 : (wz == 2) ? W2 : W3;
        dst = dw + (size_t)wz * DD * DD;
        lb = wb & 127;
    }
    float4 v[8];
    size_t base = (size_t)lb * 2048 + threadIdx.x;
#pragma unroll
    for (int it = 0; it < 8; it++)
        v[it] = *(const float4*)(src + (base + it * 256) * 4);
#pragma unroll
    for (int it = 0; it < 8; it++) {
        uint2 u; u.x = packh2(v[it].x, v[it].y); u.y = packh2(v[it].z, v[it].w);
        *(uint2*)(dst + (base + it * 256) * 4) = u;
    }
}

// ---------------------------------------------------------------------------
// fp16 GEMM: BM=256, BN=128, BK=64, 512 threads, warp grid 4m x 4n,
// warp tile 64x32 (identical per-warp inner loop to the R10/R14 winner).
// W-fragment slabs now shared by 4 m-warps -> W LDS traffic halves.
// 3-stage cp.async. smem = 159 KB -> 1 CTA/SM (16 warps, same as before).
// ---------------------------------------------------------------------------
#define APAD 72
#define WPAD 136
#define A_SZ (256 * APAD)            // 18432 halfs per stage
#define W_SZ (64 * WPAD)             // 8704 halfs per stage
#define STAGES 3
#define GEMM_SMEM (STAGES * (A_SZ + W_SZ) * 2)   // 162,816 bytes

__device__ __forceinline__ void store2(
    float* __restrict__ C, __half* __restrict__ O, int mode,
    int m, int n, float v0, float v1)
{
    if (mode == 0) {
        *(float2*)(C + (size_t)m * 1024 + n) = make_float2(v0, v1);
        return;
    }
    int b = m >> 10, s = m & 1023, h = n >> 6, d = n & 63;
    size_t idx;
    if (mode == 1) idx = (((size_t)(b * 16 + h)) * 1024 + s) * 64 + d;
    else           idx = ((((size_t)(b * 16 + h)) * 4 + (s & 3)) * 256 + (s >> 2)) * 64 + d;
    __half2 p = __floats2half2_rn(v0, v1);
    *(__half2*)(O + idx) = p;
}

__device__ __forceinline__ void gemm_body(
    const __half* __restrict__ A, const __half* __restrict__ Wm,
    const float* __restrict__ bias, float* __restrict__ C,
    __half* __restrict__ O, int mode, __half* smem)
{
    __half* sA = smem;                       // [STAGES][256][APAD]
    __half* sW = smem + STAGES * A_SZ;       // [STAGES][64][WPAD]

    const int tid = threadIdx.x;
    const int bm = blockIdx.y * 256, bn = blockIdx.x * 128;
    const int w = tid >> 5, lane = tid & 31;
    const int wm = (w & 3) * 64, wn = (w >> 2) * 32;
    const int lrow = lane & 15, lcol = (lane >> 4) << 3;

    float acc[4][4][4];
#pragma unroll
    for (int i = 0; i < 4; i++)
#pragma unroll
        for (int j = 0; j < 4; j++)
#pragma unroll
            for (int t = 0; t < 4; t++) acc[i][j][t] = 0.f;

    // staging: A tile 256x64 halfs = 2048 16B-chunks; W 64x128 = 1024 chunks
    auto stage = [&](int buf, int k0) {
#pragma unroll
        for (int j = 0; j < 4; j++) {
            int c = tid + 512 * j;
            int arow = c >> 3, aco = (c & 7) * 8;
            cp_async16(&sA[buf * A_SZ + arow * APAD + aco],
                       A + (size_t)(bm + arow) * 1024 + k0 + aco);
        }
#pragma unroll
        for (int j = 0; j < 2; j++) {
            int c = tid + 512 * j;
            int wrow = c >> 4, wco = (c & 15) * 8;
            cp_async16(&sW[buf * W_SZ + wrow * WPAD + wco],
                       Wm + (size_t)(k0 + wrow) * 1024 + bn + wco);
        }
    };

#pragma unroll
    for (int s = 0; s < STAGES - 1; s++) {
        stage(s, s * 64);
        CP_COMMIT();
    }

    for (int kt = 0; kt < 16; kt++) {
        CP_WAIT(STAGES - 2);
        __syncthreads();

        int nk = kt + STAGES - 1;
        if (nk < 16) stage(nk % STAGES, nk * 64);
        CP_COMMIT();

        const __half* cA = sA + (kt % STAGES) * A_SZ;
        const __half* cW = sW + (kt % STAGES) * W_SZ;

#pragma unroll
        for (int kk = 0; kk < 64; kk += 16) {
            uint32_t a[4][4], b_[2][4];
#pragma unroll
            for (int mt = 0; mt < 4; mt++)
                ldm_x4(a[mt], &cA[(wm + mt * 16 + lrow) * APAD + kk + lcol]);
#pragma unroll
            for (int np = 0; np < 2; np++)
                ldm_x4_t(b_[np], &cW[(kk + lrow) * WPAD + wn + np * 16 + lcol]);
#pragma unroll
            for (int mt = 0; mt < 4; mt++)
#pragma unroll
                for (int nt = 0; nt < 4; nt++)
                    mma16816(acc[mt][nt], a[mt], &b_[nt >> 1][(nt & 1) * 2]);
        }
    }

    const int g = lane >> 2, t4 = lane & 3;
#pragma unroll
    for (int mt = 0; mt < 4; mt++)
#pragma unroll
        for (int nt = 0; nt < 4; nt++) {
            int m0 = bm + wm + mt * 16 + g;
            int n0 = bn + wn + nt * 8 + t4 * 2;
            float b0 = __ldg(bias + n0), b1 = __ldg(bias + n0 + 1);
            store2(C, O, mode, m0,     n0, acc[mt][nt][0] + b0, acc[mt][nt][1] + b1);
            store2(C, O, mode, m0 + 8, n0, acc[mt][nt][2] + b0, acc[mt][nt][3] + b1);
        }
}

__global__ void __launch_bounds__(512, 1) gemm_qkv_kernel(
    const __half* __restrict__ Aq, const __half* __restrict__ Ak,
    const __half* __restrict__ Av, const __half* __restrict__ Wall,
    const float* __restrict__ bq, const float* __restrict__ bk,
    const float* __restrict__ bv,
    __half* __restrict__ Oq, __half* __restrict__ Ok, __half* __restrict__ Ov)
{
    extern __shared__ __half smem[];
    int z = blockIdx.z;
    const __half* A = (z == 0) ? Aq : (z == 1) ? Ak : Av;
    const float* bias = (z == 0) ? bq : (z == 1) ? bk : bv;
    __half* O = (z == 0) ? Oq : (z == 1) ? Ok : Ov;
    gemm_body(A, Wall + (size_t)z * DD * DD, bias, nullptr, O,
              (z == 0) ? 1 : 2, smem);
}

__global__ void __launch_bounds__(512, 1) gemm_o_kernel(
    const __half* __restrict__ A, const __half* __restrict__ Wm,
    const float* __restrict__ bias, float* __restrict__ C)
{
    extern __shared__ __half smem[];
    gemm_body(A, Wm, bias, C, nullptr, 0, smem);
}

// ---------------------------------------------------------------------------
// Fused warp-group flash attention (R16, unchanged).
// ---------------------------------------------------------------------------
#define KVS 72
#define TB (64 * KVS)
#define ATTN_SMEM (6 * TB * 2)        // 55,296 bytes

__global__ void __launch_bounds__(256, 2) attn2_kernel(
    const __half* __restrict__ qg, const __half* __restrict__ kg,
    const __half* __restrict__ vg, __half* __restrict__ out)
{
    extern __shared__ __half sm2[];
    __half* Qs = sm2;
    __half* Kb = sm2 + 2 * TB;
    __half* Vb = sm2 + 4 * TB;

    const int tid = threadIdx.x, lane = tid & 31;
    const int wg = tid >> 7;
    const int wt = tid & 127;
    const int w4 = (tid >> 5) & 3;
    const int flavor = blockIdx.x >> 8;
    const int bh = (blockIdx.x & 255) >> 2;
    const int r  = blockIdx.x & 3;
    const int qt = (flavor == 0) ? (wg ? 0 : 3) : (wg ? 1 : 2);
    const int ntb = (flavor == 0) ? 4 : 3;
    const int q0 = qt * 64;

    __half* Qw = Qs + wg * TB;

    const int wq = w4 * 16;
    const int g = lane >> 2, t4 = lane & 3;
    const int lrow = lane & 15, lcol = (lane >> 4) << 3;
    const int bnrow = ((lane >> 4) << 3) + (lane & 7);
    const int bkoff = ((lane >> 3) & 1) << 3;

    const __half* kbase = kg + (((size_t)bh * 4 + r) * 256) * 64;
    const __half* vbase = vg + (((size_t)bh * 4 + r) * 256) * 64;

#pragma unroll
    for (int j = 0; j < 4; j++) {
        int c = wt + 128 * j, row = c >> 3, co = (c & 7) * 8;
        int i = 4 * (q0 + row) + r;
        *(uint4*)&Qw[row * KVS + co] =
            *(const uint4*)(qg + ((size_t)bh * 1024 + i) * 64 + co);
    }
    __syncthreads();

    auto stage_kv = [&](int buf, int ut) {
#pragma unroll
        for (int j = 0; j < 2; j++) {
            int c = tid + 256 * j, row = c >> 3, co = (c & 7) * 8;
            cp_async16(&Kb[buf * TB + row * KVS + co],
                       kbase + (size_t)(ut * 64 + row) * 64 + co);
            cp_async16(&Vb[buf * TB + row * KVS + co],
                       vbase + (size_t)(ut * 64 + row) * 64 + co);
        }
    };
    stage_kv(0, 0);
    CP_COMMIT();

    uint32_t qf[4][4];
#pragma unroll
    for (int ks = 0; ks < 4; ks++)
        ldm_x4(qf[ks], &Qw[(wq + lrow) * KVS + ks * 16 + lcol]);

    const int i_g  = 4 * (q0 + wq + g) + r;
    const int i_g8 = i_g + 32;
    float m_g, m_g8, l_g, l_g8;
    float oacc[8][4];
#pragma unroll
    for (int nt = 0; nt < 8; nt++)
#pragma unroll
        for (int c = 0; c < 4; c++) oacc[nt][c] = 0.f;

    {
        float sg[3], sg8[3];
        const int nl_g = min(i_g, 3), nl_g8 = min(i_g8, 3);
#pragma unroll
        for (int l = 0; l < 3; l++) {
            float d0 = 0.f, d1 = 0.f;
            int jg = i_g - 1 - l, jg8 = i_g8 - 1 - l;
            if (l < nl_g) {
                const __half* kp = kg + ((((size_t)bh * 4 + (jg & 3)) * 256 + (jg >> 2)) * 64);
#pragma unroll
                for (int d = 0; d < 16; d += 2) {
                    __half2 a = *(const __half2*)&Qw[(wq + g) * KVS + t4 * 16 + d];
                    __half2 b = *(const __half2*)(kp + t4 * 16 + d);
                    d0 += __half2float(a.x) * __half2float(b.x)
                        + __half2float(a.y) * __half2float(b.y);
                }
            }
            if (l < nl_g8) {
                const __half* kp = kg + ((((size_t)bh * 4 + (jg8 & 3)) * 256 + (jg8 >> 2)) * 64);
#pragma unroll
                for (int d = 0; d < 16; d += 2) {
                    __half2 a = *(const __half2*)&Qw[(wq + g + 8) * KVS + t4 * 16 + d];
                    __half2 b = *(const __half2*)(kp + t4 * 16 + d);
                    d1 += __half2float(a.x) * __half2float(b.x)
                        + __half2float(a.y) * __half2float(b.y);
                }
            }
            d0 += __shfl_xor_sync(0xffffffffu, d0, 1);
            d0 += __shfl_xor_sync(0xffffffffu, d0, 2);
            d1 += __shfl_xor_sync(0xffffffffu, d1, 1);
            d1 += __shfl_xor_sync(0xffffffffu, d1, 2);
            sg[l]  = (l < nl_g)  ? d0 * SC : -1e30f;
            sg8[l] = (l < nl_g8) ? d1 * SC : -1e30f;
        }
        m_g  = fmaxf(fmaxf(sg[0], sg[1]), sg[2]);
        m_g8 = fmaxf(fmaxf(sg8[0], sg8[1]), sg8[2]);
        float p_g[3], p_g8[3];
        l_g = 0.f; l_g8 = 0.f;
#pragma unroll
        for (int l = 0; l < 3; l++) {
            p_g[l]  = (l < nl_g)  ? ex2f(sg[l] - m_g)   : 0.f;
            p_g8[l] = (l < nl_g8) ? ex2f(sg8[l] - m_g8) : 0.f;
            l_g += p_g[l]; l_g8 += p_g8[l];
        }
#pragma unroll
        for (int l = 0; l < 3; l++) {
            int jg = i_g - 1 - l, jg8 = i_g8 - 1 - l;
            if (l < nl_g) {
                const __half* vp = vg + ((((size_t)bh * 4 + (jg & 3)) * 256 + (jg >> 2)) * 64);
#pragma unroll
                for (int nt = 0; nt < 8; nt++) {
                    __half2 v2 = *(const __half2*)(vp + nt * 8 + t4 * 2);
                    oacc[nt][0] += p_g[l] * __half2float(v2.x);
                    oacc[nt][1] += p_g[l] * __half2float(v2.y);
                }
            }
            if (l < nl_g8) {
                const __half* vp = vg + ((((size_t)bh * 4 + (jg8 & 3)) * 256 + (jg8 >> 2)) * 64);
#pragma unroll
                for (int nt = 0; nt < 8; nt++) {
                    __half2 v2 = *(const __half2*)(vp + nt * 8 + t4 * 2);
                    oacc[nt][2] += p_g8[l] * __half2float(v2.x);
                    oacc[nt][3] += p_g8[l] * __half2float(v2.y);
                }
            }
        }
    }

    int buf = 0;
    for (int ut = 0; ut < ntb; ut++) {
        CP_WAIT(0);
        __syncthreads();
        if (ut + 1 < ntb) {
            stage_kv(buf ^ 1, ut + 1);
            CP_COMMIT();
        }

        if (ut <= qt) {
            float acc[8][4];
#pragma unroll
            for (int nt = 0; nt < 8; nt++)
#pragma unroll
                for (int c = 0; c < 4; c++) acc[nt][c] = 0.f;
#pragma unroll
            for (int ks = 0; ks < 4; ks++)
#pragma unroll
                for (int nb = 0; nb < 4; nb++) {
                    uint32_t bh4[4];
                    ldm_x4(bh4, &Kb[buf * TB + (nb * 16 + bnrow) * KVS + ks * 16 + bkoff]);
                    mma16816(acc[nb * 2 + 0], qf[ks], &bh4[0]);
                    mma16816(acc[nb * 2 + 1], qf[ks], &bh4[2]);
                }

            if (ut == qt) {
                const int lim_g = wq + g, lim_g8 = wq + g + 8;
#pragma unroll
                for (int nt = 0; nt < 8; nt++) {
                    int u0 = nt * 8 + t4 * 2;
                    acc[nt][0] = (u0     <= lim_g)  ? acc[nt][0] * SC : -1e30f;
                    acc[nt][1] = (u0 + 1 <= lim_g)  ? acc[nt][1] * SC : -1e30f;
                    acc[nt][2] = (u0     <= lim_g8) ? acc[nt][2] * SC : -1e30f;
                    acc[nt][3] = (u0 + 1 <= lim_g8) ? acc[nt][3] * SC : -1e30f;
                }
            } else {
#pragma unroll
                for (int nt = 0; nt < 8; nt++)
#pragma unroll
                    for (int c = 0; c < 4; c++) acc[nt][c] *= SC;
            }

            float tm_g = -1e30f, tm_g8 = -1e30f;
#pragma unroll
            for (int nt = 0; nt < 8; nt++) {
                tm_g  = fmaxf(tm_g,  fmaxf(acc[nt][0], acc[nt][1]));
                tm_g8 = fmaxf(tm_g8, fmaxf(acc[nt][2], acc[nt][3]));
            }
            tm_g  = fmaxf(tm_g,  __shfl_xor_sync(0xffffffffu, tm_g, 1));
            tm_g  = fmaxf(tm_g,  __shfl_xor_sync(0xffffffffu, tm_g, 2));
            tm_g8 = fmaxf(tm_g8, __shfl_xor_sync(0xffffffffu, tm_g8, 1));
            tm_g8 = fmaxf(tm_g8, __shfl_xor_sync(0xffffffffu, tm_g8, 2));

            float mn_g = fmaxf(m_g, tm_g), mn_g8 = fmaxf(m_g8, tm_g8);
            float al_g = ex2f(m_g - mn_g), al_g8 = ex2f(m_g8 - mn_g8);
            m_g = mn_g; m_g8 = mn_g8;

            uint32_t pb[8][2];
            float ps_g = 0.f, ps_g8 = 0.f;
#pragma unroll
            for (int nt = 0; nt < 8; nt++) {
                pb[nt][0] = ex2_h2(acc[nt][0] - mn_g,  acc[nt][1] - mn_g);
                pb[nt][1] = ex2_h2(acc[nt][2] - mn_g8, acc[nt][3] - mn_g8);
                ps_g  += sum_h2(pb[nt][0]);
                ps_g8 += sum_h2(pb[nt][1]);
            }
            ps_g  += __shfl_xor_sync(0xffffffffu, ps_g, 1);
            ps_g  += __shfl_xor_sync(0xffffffffu, ps_g, 2);
            ps_g8 += __shfl_xor_sync(0xffffffffu, ps_g8, 1);
            ps_g8 += __shfl_xor_sync(0xffffffffu, ps_g8, 2);
            l_g = l_g * al_g + ps_g;
            l_g8 = l_g8 * al_g8 + ps_g8;
#pragma unroll
            for (int nt = 0; nt < 8; nt++) {
                oacc[nt][0] *= al_g;  oacc[nt][1] *= al_g;
                oacc[nt][2] *= al_g8; oacc[nt][3] *= al_g8;
            }

#pragma unroll
            for (int ks = 0; ks < 4; ks++) {
                uint32_t pa[4];
                pa[0] = pb[2 * ks][0];
                pa[1] = pb[2 * ks][1];
                pa[2] = pb[2 * ks + 1][0];
                pa[3] = pb[2 * ks + 1][1];
#pragma unroll
                for (int nb = 0; nb < 4; nb++) {
                    uint32_t vh4[4];
                    ldm_x4_t(vh4, &Vb[buf * TB + (ks * 16 + lrow) * KVS + nb * 16 + lcol]);
                    mma16816(oacc[nb * 2 + 0], pa, &vh4[0]);
                    mma16816(oacc[nb * 2 + 1], pa, &vh4[2]);
                }
            }
        }
        buf ^= 1;
    }

    {
        float inv_g = 1.0f / l_g, inv_g8 = 1.0f / l_g8;
#pragma unroll
        for (int nt = 0; nt < 8; nt++) {
            *(__half2*)&Qw[(wq + g) * KVS + nt * 8 + t4 * 2] =
                __floats2half2_rn(oacc[nt][0] * inv_g, oacc[nt][1] * inv_g);
            *(__half2*)&Qw[(wq + g + 8) * KVS + nt * 8 + t4 * 2] =
                __floats2half2_rn(oacc[nt][2] * inv_g8, oacc[nt][3] * inv_g8);
        }
    }
    __syncthreads();
    {
        int bb = bh >> 4, h = bh & 15;
#pragma unroll
        for (int j = 0; j < 4; j++) {
            int c = wt + 128 * j, row = c >> 3, co = (c & 7) * 8;
            int i = 4 * (q0 + row) + r;
            *(uint4*)(out + ((size_t)(bb * 1024 + i)) * 1024 + h * 64 + co) =
                *(const uint4*)&Qw[row * KVS + co];
        }
    }
}

// ---------------------------------------------------------------------------
extern "C" void kernel_launch(void* const* d_in, const int* in_sizes, int n_in,
                              void* d_out, int out_size)
{
    const float* Q  = (const float*)d_in[0];
    const float* K  = (const float*)d_in[1];
    const float* V  = (const float*)d_in[2];
    const float* Wq = (const float*)d_in[3];
    const float* bq = (const float*)d_in[4];
    const float* Wk = (const float*)d_in[5];
    const float* bk = (const float*)d_in[6];
    const float* Wv = (const float*)d_in[7];
    const float* bv = (const float*)d_in[8];
    const float* Wo = (const float*)d_in[9];
    const float* bo = (const float*)d_in[10];
    float* out = (float*)d_out;

    __half *pqin, *pkin, *pvin, *pw, *pq, *pk, *pv, *pah;
    cudaGetSymbolAddress((void**)&pqin, g_qin);
    cudaGetSymbolAddress((void**)&pkin, g_kin);
    cudaGetSymbolAddress((void**)&pvin, g_vin);
    cudaGetSymbolAddress((void**)&pw, g_w);
    cudaGetSymbolAddress((void**)&pq, g_q);
    cudaGetSymbolAddress((void**)&pk, g_k);
    cudaGetSymbolAddress((void**)&pv, g_v);
    cudaGetSymbolAddress((void**)&pah, g_attn);

    cudaFuncSetAttribute(gemm_qkv_kernel,
                         cudaFuncAttributeMaxDynamicSharedMemorySize, GEMM_SMEM);
    cudaFuncSetAttribute(gemm_o_kernel,
                         cudaFuncAttributeMaxDynamicSharedMemorySize, GEMM_SMEM);
    cudaFuncSetAttribute(attn2_kernel,
                         cudaFuncAttributeMaxDynamicSharedMemorySize, ATTN_SMEM);

    convall_kernel<<<2048, 256>>>(Q, K, V, Wq, Wk, Wv, Wo, pqin, pkin, pvin, pw);

    gemm_qkv_kernel<<<dim3(8, 16, 3), 512, GEMM_SMEM>>>(
        pqin, pkin, pvin, pw, bq, bk, bv, pq, pk, pv);

    attn2_kernel<<<512, 256, ATTN_SMEM>>>(pq, pk, pv, pah);

    gemm_o_kernel<<<dim3(8, 16), 512, GEMM_SMEM>>>(
        pah, pw + 3 * (size_t)DD * DD, bo, out);
}